// round 15
// baseline (speedup 1.0000x reference)
#include <cuda_runtime.h>
#include <cuda_pipeline.h>
#include <math.h>

#define NN 50000
#define NE 800000
#define HD 128
#define NH 8
#define NBLK 196   // ceil(NN/256)

typedef unsigned long long ull;

// ---------------- device scratch (static, no allocation) ----------------
__device__ float g_P[NN*HD];      // x @ W0 (layer-1 projection)
__device__ float g_h1[NN*HD];     // layer-1 output after elu
__device__ float g_TU[NN*256];    // [U0 | U1] per src node
__device__ float g_TV[NN*256];    // [V0 | V1] per dst node
__device__ float g_tab[128*128];  // structural reward lookup: 10*(ts(do,di)+bs2)
__device__ int   g_src[NE], g_dst[NE];
__device__ int   g_degout[NN], g_degin[NN];
__device__ int   g_rps[NN+1], g_rpd[NN+1];
__device__ int   g_curs[NN], g_curd[NN];
__device__ int   g_part[2][NBLK];
__device__ int4  g_er[NE];        // CSR order: (dst, rstr10_bits, r0_bits, r1_bits)
__device__ int2  g_csc[NE];       // CSC order: (csr_pos, src)
__device__ float g_als0[NN*NH], g_ald0[NN*NH], g_als1[NN*NH], g_ald1[NN*NH];
__device__ float g_Was[HD*NH], g_Wad[HD*NH];
__device__ float2 g_ac[NE];       // attention (a1, a2) in CSR order
__device__ float2 g_Vp[2][NN];    // V*10 packed (hop0,hop1), double-buffered
__device__ float g_loss;
__device__ int   g_is64;

__device__ __forceinline__ float* sel_node(int s) {
    switch (s) { case 0: return g_P; case 1: return g_TU; default: return g_TV; }
}

// ---------------- f32x2 packed math helpers (Blackwell) ----------------
__device__ __forceinline__ ull packf2(float lo, float hi) {
    ull r;
    asm("mov.b64 %0, {%1, %2};" : "=l"(r) : "f"(lo), "f"(hi));
    return r;
}
__device__ __forceinline__ void unpackf2(ull v, float& lo, float& hi) {
    asm("mov.b64 {%0, %1}, %2;" : "=f"(lo), "=f"(hi) : "l"(v));
}
__device__ __forceinline__ void fmaf2(ull& d, ull a, ull b) {
    asm("fma.rn.f32x2 %0, %1, %2, %0;" : "+l"(d) : "l"(a), "l"(b));
}

// ---------------- helpers ----------------
__device__ __forceinline__ void olse(float& m, float& s, float q) {
    if (q > m) { s = s * __expf(m - q) + 1.f; m = q; }
    else       { s += __expf(q - m); }
}
__device__ __forceinline__ void wcomb(float& m, float& s) {
    #pragma unroll
    for (int off = 16; off; off >>= 1) {
        float mo = __shfl_xor_sync(0xffffffffu, m, off);
        float so = __shfl_xor_sync(0xffffffffu, s, off);
        float M  = fmaxf(m, mo);
        float ea = (m  == M) ? 1.f : __expf(m  - M);
        float eb = (mo == M) ? 1.f : __expf(mo - M);
        s = s * ea + so * eb; m = M;
    }
}
__device__ __forceinline__ float wsum(float v) {
    #pragma unroll
    for (int off = 16; off; off >>= 1) v += __shfl_xor_sync(0xffffffffu, v, off);
    return v;
}
__device__ __forceinline__ int wsumi(int v) {
    #pragma unroll
    for (int off = 16; off; off >>= 1) v += __shfl_xor_sync(0xffffffffu, v, off);
    return v;
}

// ---------------- kernels ----------------
__global__ void k_init() {
    int i = blockIdx.x * blockDim.x + threadIdx.x;
    if (i < NN) { g_degout[i] = 0; g_degin[i] = 0; }
    if (i == 0) { g_loss = 0.f; g_is64 = 1; }
}

__global__ void k_detect(const int* __restrict__ ei32) {
    int i = blockIdx.x * blockDim.x + threadIdx.x;
    if (i < 65536) {
        if (ei32[2 * i + 1] != 0) g_is64 = 0;
    }
}

// Structural reward lookup table: tab[do][di] = 10*(mlp2([do,di,log1p,log1p])+bs2)
__global__ void k_tab(const float* __restrict__ Ws1, const float* __restrict__ bs1,
                      const float* __restrict__ ws2, const float* __restrict__ b2s) {
    int gw = (int)((blockIdx.x * blockDim.x + threadIdx.x) >> 5);
    int lane = threadIdx.x & 31;
    int nw = (int)((gridDim.x * blockDim.x) >> 5);
    float w1[4], w2[4], w3[4], w4[4], bb[4], wk[4];
    #pragma unroll
    for (int j = 0; j < 4; j++) {
        int k = lane * 4 + j;
        w1[j] = Ws1[k]; w2[j] = Ws1[128 + k]; w3[j] = Ws1[256 + k]; w4[j] = Ws1[384 + k];
        bb[j] = bs1[k]; wk[j] = ws2[k];
    }
    float b2v = *b2s;
    for (int e = gw; e < 128 * 128; e += nw) {
        int dO = e >> 7, dI = e & 127;
        float fo = (float)dO, fi = (float)dI;
        float lo = log1pf(fo), li = log1pf(fi);
        float t = 0.f;
        #pragma unroll
        for (int j = 0; j < 4; j++) {
            float us = fo * w1[j] + lo * w3[j] + bb[j];
            float vs = fi * w2[j] + li * w4[j];
            t += fmaxf(us + vs, 0.f) * wk[j];
        }
        t = wsum(t);
        if (lane == 0) g_tab[e] = 10.f * (t + b2v);
    }
}

__global__ void k_prep(const void* __restrict__ eiv) {
    int e = blockIdx.x * blockDim.x + threadIdx.x;
    if (e >= NE) return;
    int s, d;
    if (g_is64) {
        const long long* ei = (const long long*)eiv;
        s = (int)ei[e]; d = (int)ei[NE + e];
    } else {
        const int* ei = (const int*)eiv;
        s = ei[e]; d = ei[NE + e];
    }
    s = min(max(s, 0), NN - 1);
    d = min(max(d, 0), NN - 1);
    g_src[e] = s; g_dst[e] = d;
    atomicAdd(&g_degout[s], 1);
    atomicAdd(&g_degin[d], 1);
}

__global__ void k_scan1() {
    int a = blockIdx.x >= NBLK;
    int b = blockIdx.x - a * NBLK;
    const int* deg = a ? g_degin : g_degout;
    int i = b * 256 + threadIdx.x;
    int v = (i < NN) ? deg[i] : 0;
    __shared__ int sw[8];
    int ws = wsumi(v);
    if ((threadIdx.x & 31) == 0) sw[threadIdx.x >> 5] = ws;
    __syncthreads();
    if (threadIdx.x == 0) {
        int t = 0;
        #pragma unroll
        for (int j = 0; j < 8; j++) t += sw[j];
        g_part[a][b] = t;
    }
}

__global__ void k_scan2() {
    int a = threadIdx.x >> 8;
    int t = threadIdx.x & 255;
    __shared__ int sh[2][256];
    int v = (t < NBLK) ? g_part[a][t] : 0;
    sh[a][t] = v;
    __syncthreads();
    for (int off = 1; off < 256; off <<= 1) {
        int u = (t >= off) ? sh[a][t - off] : 0;
        __syncthreads();
        sh[a][t] += u;
        __syncthreads();
    }
    if (t < NBLK) g_part[a][t] = sh[a][t] - v;
    if (t == 255) {
        if (a) g_rpd[NN] = sh[1][255]; else g_rps[NN] = sh[0][255];
    }
}

__global__ void k_scan3() {
    int a = blockIdx.x >= NBLK;
    int b = blockIdx.x - a * NBLK;
    const int* deg = a ? g_degin : g_degout;
    int* rp  = a ? g_rpd  : g_rps;
    int* cur = a ? g_curd : g_curs;
    int i = b * 256 + threadIdx.x;
    int v = (i < NN) ? deg[i] : 0;
    __shared__ int sh[256];
    sh[threadIdx.x] = v;
    __syncthreads();
    for (int off = 1; off < 256; off <<= 1) {
        int u = (threadIdx.x >= off) ? sh[threadIdx.x - off] : 0;
        __syncthreads();
        sh[threadIdx.x] += u;
        __syncthreads();
    }
    if (i < NN) {
        int excl = sh[threadIdx.x] - v + g_part[a][b];
        rp[i] = excl; cur[i] = excl;
    }
}

__global__ void k_fill() {
    int e = blockIdx.x * blockDim.x + threadIdx.x;
    if (e >= NE) return;
    int s = g_src[e], d = g_dst[e];
    int dO = g_degout[s], dI = g_degin[d];
    float r = (dO < 128 && dI < 128) ? g_tab[dO * 128 + dI]
                                     : __int_as_float(0x7fc00000);  // NaN sentinel
    int p = atomicAdd(&g_curs[s], 1);
    g_er[p] = make_int4(d, __float_as_int(r), 0, 0);
    int q = atomicAdd(&g_curd[d], 1);
    g_csc[q] = make_int2(p, s);
}

// Batched GEMM: up to 3 (dsel,coff,B,bias) configs selected by blockIdx.y,
// sharing A. 128x128 tile, 8x8 micro via fma.rn.f32x2. Double-buffered smem:
// B tiles via cp.async, A tiles prefetched one tile ahead.
__global__ void __launch_bounds__(256, 2) k_gemmB(
        const float* __restrict__ aext,
        int d0, int c0, const float* __restrict__ B0, const float* __restrict__ bias0,
        int d1, int c1, const float* __restrict__ B1, const float* __restrict__ bias1,
        int d2, int c2, const float* __restrict__ B2, const float* __restrict__ bias2,
        int M) {
    const float* A = aext ? aext : g_h1;
    int dsel, coff;
    const float *B, *bias;
    if (blockIdx.y == 0)      { dsel = d0; coff = c0; B = B0; bias = bias0; }
    else if (blockIdx.y == 1) { dsel = d1; coff = c1; B = B1; bias = bias1; }
    else                      { dsel = d2; coff = c2; B = B2; bias = bias2; }
    float* C = sel_node(dsel);
    int cs = (dsel == 0) ? 128 : 256;
    __shared__ float Ast[2][16][136];
    __shared__ float Bs[2][16][128];
    int bm = blockIdx.x * 128;
    int tid = threadIdx.x;
    int tr = tid >> 4, tc = tid & 15;
    int ar = tid >> 2, ac = (tid & 3) << 2;
    int br = tid >> 5, bc = (tid & 31) << 2;
    ull acc[8][4];
    #pragma unroll
    for (int i = 0; i < 8; i++)
        #pragma unroll
        for (int j = 0; j < 4; j++) acc[i][j] = 0ull;

    float4 pa0, pa1;

    {
        float4 v0 = make_float4(0.f, 0.f, 0.f, 0.f), v1 = v0;
        if (bm + ar < M)       v0 = *(const float4*)&A[(size_t)(bm + ar) * HD + ac];
        if (bm + ar + 64 < M)  v1 = *(const float4*)&A[(size_t)(bm + ar + 64) * HD + ac];
        Ast[0][ac][ar] = v0.x; Ast[0][ac+1][ar] = v0.y; Ast[0][ac+2][ar] = v0.z; Ast[0][ac+3][ar] = v0.w;
        Ast[0][ac][ar+64] = v1.x; Ast[0][ac+1][ar+64] = v1.y; Ast[0][ac+2][ar+64] = v1.z; Ast[0][ac+3][ar+64] = v1.w;
        __pipeline_memcpy_async(&Bs[0][br][bc],     &B[(size_t)br * HD + bc], 16);
        __pipeline_memcpy_async(&Bs[0][br + 8][bc], &B[(size_t)(br + 8) * HD + bc], 16);
        __pipeline_commit();
        __pipeline_wait_prior(0);
        pa0 = make_float4(0.f, 0.f, 0.f, 0.f); pa1 = pa0;
        if (bm + ar < M)       pa0 = *(const float4*)&A[(size_t)(bm + ar) * HD + 16 + ac];
        if (bm + ar + 64 < M)  pa1 = *(const float4*)&A[(size_t)(bm + ar + 64) * HD + 16 + ac];
        __pipeline_memcpy_async(&Bs[1][br][bc],     &B[(size_t)(16 + br) * HD + bc], 16);
        __pipeline_memcpy_async(&Bs[1][br + 8][bc], &B[(size_t)(16 + br + 8) * HD + bc], 16);
        __pipeline_commit();
        __syncthreads();
    }

    #pragma unroll 1
    for (int t = 0; t < 8; t++) {
        int cur = t & 1;
        #pragma unroll
        for (int k = 0; k < 16; k++) {
            float4 a0 = *(float4*)&Ast[cur][k][tr * 8];
            float4 a1 = *(float4*)&Ast[cur][k][tr * 8 + 4];
            float4 b0 = *(float4*)&Bs[cur][k][tc * 8];
            float4 b1 = *(float4*)&Bs[cur][k][tc * 8 + 4];
            ull b2[4] = { packf2(b0.x, b0.y), packf2(b0.z, b0.w),
                          packf2(b1.x, b1.y), packf2(b1.z, b1.w) };
            float av[8] = {a0.x, a0.y, a0.z, a0.w, a1.x, a1.y, a1.z, a1.w};
            #pragma unroll
            for (int i = 0; i < 8; i++) {
                ull af = packf2(av[i], av[i]);
                #pragma unroll
                for (int j = 0; j < 4; j++) fmaf2(acc[i][j], af, b2[j]);
            }
        }
        if (t < 7) {
            int nxt = cur ^ 1;
            __syncthreads();
            Ast[nxt][ac][ar] = pa0.x; Ast[nxt][ac+1][ar] = pa0.y;
            Ast[nxt][ac+2][ar] = pa0.z; Ast[nxt][ac+3][ar] = pa0.w;
            Ast[nxt][ac][ar+64] = pa1.x; Ast[nxt][ac+1][ar+64] = pa1.y;
            Ast[nxt][ac+2][ar+64] = pa1.z; Ast[nxt][ac+3][ar+64] = pa1.w;
            __pipeline_wait_prior(0);
            if (t < 6) {
                int k0 = (t + 2) * 16;
                pa0 = make_float4(0.f, 0.f, 0.f, 0.f); pa1 = pa0;
                if (bm + ar < M)      pa0 = *(const float4*)&A[(size_t)(bm + ar) * HD + k0 + ac];
                if (bm + ar + 64 < M) pa1 = *(const float4*)&A[(size_t)(bm + ar + 64) * HD + k0 + ac];
                __pipeline_memcpy_async(&Bs[cur][br][bc],     &B[(size_t)(k0 + br) * HD + bc], 16);
                __pipeline_memcpy_async(&Bs[cur][br + 8][bc], &B[(size_t)(k0 + br + 8) * HD + bc], 16);
                __pipeline_commit();
            }
            __syncthreads();
        }
    }
    #pragma unroll
    for (int i = 0; i < 8; i++) {
        int row = bm + tr * 8 + i;
        if (row < M) {
            #pragma unroll
            for (int j = 0; j < 4; j++) {
                float lo, hi;
                unpackf2(acc[i][j], lo, hi);
                int col = tc * 8 + j * 2;
                if (bias) { lo += bias[col]; hi += bias[col + 1]; }
                C[(size_t)row * cs + coff + col]     = lo;
                C[(size_t)row * cs + coff + col + 1] = hi;
            }
        }
    }
}

// al_s0/al_d0 from P (warp per node)
__global__ void k_alP(const float* __restrict__ as0, const float* __restrict__ ad0) {
    int g = blockIdx.x * blockDim.x + threadIdx.x;
    int w = g >> 5, lane = g & 31;
    if (w >= NN) return;
    int h = lane >> 2;
    int off = (lane & 3) * 4;
    float4 v = *(const float4*)&g_P[(size_t)w * HD + lane * 4];
    const float* a = &as0[h * 16 + off];
    const float* b = &ad0[h * 16 + off];
    float ps = v.x * a[0] + v.y * a[1] + v.z * a[2] + v.w * a[3];
    float pd = v.x * b[0] + v.y * b[1] + v.z * b[2] + v.w * b[3];
    ps += __shfl_xor_sync(0xffffffffu, ps, 1);
    ps += __shfl_xor_sync(0xffffffffu, ps, 2);
    pd += __shfl_xor_sync(0xffffffffu, pd, 1);
    pd += __shfl_xor_sync(0xffffffffu, pd, 2);
    if ((lane & 3) == 0) { g_als0[w * NH + h] = ps; g_ald0[w * NH + h] = pd; }
}

// GAT layer 1: softmax over incoming edges + aggregation + elu. Warp per dst node.
__global__ void __launch_bounds__(256) k_gat1() {
    __shared__ float s_at[8][256];
    __shared__ int   s_sc[8][32];
    int g = blockIdx.x * blockDim.x + threadIdx.x;
    int w = g >> 5, lane = g & 31, wl = threadIdx.x >> 5;
    if (w >= NN) return;
    int beg = g_rpd[w], end = g_rpd[w + 1];
    float ald[8];
    #pragma unroll
    for (int h = 0; h < 8; h++) ald[h] = g_ald0[w * NH + h];
    float m[8], s[8], ec[8];
    #pragma unroll
    for (int h = 0; h < 8; h++) { m[h] = -INFINITY; s[h] = 0.f; ec[h] = 0.f; }
    for (int p = beg + lane; p < end; p += 32) {
        int sn = g_csc[p].y;
        const float4* ap = (const float4*)&g_als0[sn * NH];
        float4 a0 = ap[0], a1 = ap[1];
        float ev[8] = {a0.x, a0.y, a0.z, a0.w, a1.x, a1.y, a1.z, a1.w};
        #pragma unroll
        for (int h = 0; h < 8; h++) {
            float e = ev[h] + ald[h];
            e = (e > 0.f) ? e : 0.2f * e;
            if (p - beg < 32) ec[h] = e;
            olse(m[h], s[h], e);
        }
    }
    #pragma unroll
    for (int h = 0; h < 8; h++) wcomb(m[h], s[h]);
    float lse[8];
    #pragma unroll
    for (int h = 0; h < 8; h++) lse[h] = m[h] + __logf(s[h]);

    ull accp0 = 0ull, accp1 = 0ull;
    int h0 = lane >> 2;
    for (int t0 = beg; t0 < end; t0 += 32) {
        int p = t0 + lane;
        int cnt = min(32, end - t0);
        if (p < end) {
            int2 cs = g_csc[p];
            int sn = cs.y;
            float ev[8];
            if (t0 == beg) {
                #pragma unroll
                for (int h = 0; h < 8; h++) ev[h] = ec[h];
            } else {
                const float4* ap = (const float4*)&g_als0[sn * NH];
                float4 a0 = ap[0], a1 = ap[1];
                float tv[8] = {a0.x, a0.y, a0.z, a0.w, a1.x, a1.y, a1.z, a1.w};
                #pragma unroll
                for (int h = 0; h < 8; h++) {
                    float e = tv[h] + ald[h];
                    ev[h] = (e > 0.f) ? e : 0.2f * e;
                }
            }
            float asum = 0.f;
            #pragma unroll
            for (int h = 0; h < 8; h++) {
                float a = __expf(ev[h] - lse[h]);
                s_at[wl][lane * 8 + h] = a;
                asum += a;
            }
            g_ac[cs.x].x = asum * 0.125f;
            s_sc[wl][lane] = sn;
        }
        __syncwarp();
        for (int j = 0; j < cnt; j++) {
            int sj = s_sc[wl][j];
            float a = s_at[wl][j * 8 + h0];
            float4 pv = *(const float4*)&g_P[(size_t)sj * HD + lane * 4];
            ull af = packf2(a, a);
            fmaf2(accp0, af, packf2(pv.x, pv.y));
            fmaf2(accp1, af, packf2(pv.z, pv.w));
        }
        __syncwarp();
    }
    float4 hv;
    unpackf2(accp0, hv.x, hv.y);
    unpackf2(accp1, hv.z, hv.w);
    hv.x = (hv.x > 0.f) ? hv.x : expm1f(hv.x);
    hv.y = (hv.y > 0.f) ? hv.y : expm1f(hv.y);
    hv.z = (hv.z > 0.f) ? hv.z : expm1f(hv.z);
    hv.w = (hv.w > 0.f) ? hv.w : expm1f(hv.w);
    *(float4*)&g_h1[(size_t)w * HD + lane * 4] = hv;
}

// Fold W1 with per-head attention vectors
__global__ void k_Wa(const float* __restrict__ W1, const float* __restrict__ as1,
                     const float* __restrict__ ad1) {
    int k = threadIdx.x;
    #pragma unroll
    for (int h = 0; h < 8; h++) {
        float ss = 0.f, sd = 0.f;
        #pragma unroll
        for (int d = 0; d < 16; d++) {
            float wv = W1[k * HD + h * 16 + d];
            ss += wv * as1[h * 16 + d];
            sd += wv * ad1[h * 16 + d];
        }
        g_Was[k * 8 + h] = ss;
        g_Wad[k * 8 + h] = sd;
    }
}

// al_s1/al_d1 = h1 @ Wa (warp per node)
__global__ void k_al2() {
    int g = blockIdx.x * blockDim.x + threadIdx.x;
    int w = g >> 5, lane = g & 31;
    if (w >= NN) return;
    float4 v = *(const float4*)&g_h1[(size_t)w * HD + lane * 4];
    float xv[4] = {v.x, v.y, v.z, v.w};
    float ps[8], pd[8];
    #pragma unroll
    for (int h = 0; h < 8; h++) { ps[h] = 0.f; pd[h] = 0.f; }
    #pragma unroll
    for (int j = 0; j < 4; j++) {
        int k = lane * 4 + j;
        const float* was = &g_Was[k * 8];
        const float* wad = &g_Wad[k * 8];
        #pragma unroll
        for (int h = 0; h < 8; h++) {
            ps[h] = fmaf(xv[j], was[h], ps[h]);
            pd[h] = fmaf(xv[j], wad[h], pd[h]);
        }
    }
    #pragma unroll
    for (int off = 16; off; off >>= 1)
        #pragma unroll
        for (int h = 0; h < 8; h++) {
            ps[h] += __shfl_xor_sync(0xffffffffu, ps[h], off);
            pd[h] += __shfl_xor_sync(0xffffffffu, pd[h], off);
        }
    if (lane == 0) {
        #pragma unroll
        for (int h = 0; h < 8; h++) {
            g_als1[w * NH + h] = ps[h];
            g_ald1[w * NH + h] = pd[h];
        }
    }
}

// Layer-2 attention only (a2). Warp per dst node; float4x2 gathers.
__global__ void k_attn2() {
    int g = blockIdx.x * blockDim.x + threadIdx.x;
    int w = g >> 5, lane = g & 31;
    if (w >= NN) return;
    int beg = g_rpd[w], end = g_rpd[w + 1];
    if (beg == end) return;
    float ald[8];
    #pragma unroll
    for (int h = 0; h < 8; h++) ald[h] = g_ald1[w * NH + h];
    float m[8], s[8], ec[8];
    #pragma unroll
    for (int h = 0; h < 8; h++) { m[h] = -INFINITY; s[h] = 0.f; ec[h] = 0.f; }
    for (int p = beg + lane; p < end; p += 32) {
        int sn = g_csc[p].y;
        const float4* ap = (const float4*)&g_als1[sn * NH];
        float4 a0 = ap[0], a1 = ap[1];
        float ev[8] = {a0.x, a0.y, a0.z, a0.w, a1.x, a1.y, a1.z, a1.w};
        #pragma unroll
        for (int h = 0; h < 8; h++) {
            float e = ev[h] + ald[h];
            e = (e > 0.f) ? e : 0.2f * e;
            if (p - beg < 32) ec[h] = e;
            olse(m[h], s[h], e);
        }
    }
    #pragma unroll
    for (int h = 0; h < 8; h++) wcomb(m[h], s[h]);
    float lse[8];
    #pragma unroll
    for (int h = 0; h < 8; h++) lse[h] = m[h] + __logf(s[h]);
    for (int p = beg + lane; p < end; p += 32) {
        int2 cs = g_csc[p];
        float asum = 0.f;
        if (p - beg < 32) {
            #pragma unroll
            for (int h = 0; h < 8; h++) asum += __expf(ec[h] - lse[h]);
        } else {
            int sn = cs.y;
            const float4* ap = (const float4*)&g_als1[sn * NH];
            float4 a0 = ap[0], a1 = ap[1];
            float ev[8] = {a0.x, a0.y, a0.z, a0.w, a1.x, a1.y, a1.z, a1.w};
            #pragma unroll
            for (int h = 0; h < 8; h++) {
                float e = ev[h] + ald[h];
                e = (e > 0.f) ? e : 0.2f * e;
                asum += __expf(e - lse[h]);
            }
        }
        g_ac[cs.x].y = asum * 0.125f;
    }
}

// Fused semantic reward kernel + SVI iteration 0 (V0=0 => Q=r => V1=lse(r)).
// Reads (dst, rstr) from g_er, writes (r0, r1) back into .zw.
__global__ void __launch_bounds__(256) k_rewards(const float* __restrict__ w2m,
                                                 const float* __restrict__ b2m,
                                                 const float* __restrict__ lam,
                                                 const float* __restrict__ Ws1,
                                                 const float* __restrict__ bs1,
                                                 const float* __restrict__ ws2,
                                                 const float* __restrict__ b2s) {
    int g = blockIdx.x * blockDim.x + threadIdx.x;
    int w = g >> 5, lane = g & 31;
    if (w >= NN) return;
    int beg = g_rps[w], end = g_rps[w + 1];
    if (beg == end) {
        if (lane == 0) g_Vp[1][w] = make_float2(0.f, 0.f);
        return;
    }
    size_t ro = (size_t)w * 256 + lane * 4;
    float4 u0 = *(const float4*)&g_TU[ro];
    float4 u1 = *(const float4*)&g_TU[ro + 128];
    float4 wm = *(const float4*)&w2m[lane * 4];
    float bm2v = *b2m, lam10 = 10.f * (*lam);
    float m0 = -INFINITY, s0 = 0.f, m1 = -INFINITY, s1 = 0.f;
    for (int p = beg; p < end; p++) {
        int4 er = g_er[p];
        int d = er.x;
        float rstr10 = __int_as_float(er.y);
        size_t co = (size_t)d * 256 + lane * 4;
        float4 v0 = *(const float4*)&g_TV[co];
        float4 v1 = *(const float4*)&g_TV[co + 128];
        float t0 = fmaxf(u0.x + v0.x, 0.f) * wm.x + fmaxf(u0.y + v0.y, 0.f) * wm.y +
                   fmaxf(u0.z + v0.z, 0.f) * wm.z + fmaxf(u0.w + v0.w, 0.f) * wm.w;
        float t1 = fmaxf(u1.x + v1.x, 0.f) * wm.x + fmaxf(u1.y + v1.y, 0.f) * wm.y +
                   fmaxf(u1.z + v1.z, 0.f) * wm.z + fmaxf(u1.w + v1.w, 0.f) * wm.w;
        #pragma unroll
        for (int off = 16; off; off >>= 1) {
            t0 += __shfl_xor_sync(0xffffffffu, t0, off);
            t1 += __shfl_xor_sync(0xffffffffu, t1, off);
        }
        if (!(rstr10 == rstr10)) {   // sentinel: exact structural compute (never in practice)
            float fo = (float)g_degout[w], fi = (float)g_degin[d];
            float lo = log1pf(fo), li = log1pf(fi);
            float ts = 0.f;
            #pragma unroll
            for (int j = 0; j < 4; j++) {
                int k = lane * 4 + j;
                float us = fo * Ws1[k] + lo * Ws1[256 + k] + bs1[k];
                float vs = fi * Ws1[128 + k] + li * Ws1[384 + k];
                ts += fmaxf(us + vs, 0.f) * ws2[k];
            }
            ts = wsum(ts);
            rstr10 = 10.f * (ts + *b2s);
        }
        float r0 = rstr10 + lam10 * (t0 + bm2v);
        float r1 = rstr10 + lam10 * (t1 + bm2v);
        if (lane == 0) *(float2*)&g_er[p].z = make_float2(r0, r1);
        olse(m0, s0, r0);
        olse(m1, s1, r1);
    }
    if (lane == 0)
        g_Vp[1][w] = make_float2(m0 + __logf(s0), m1 + __logf(s1));
}

// One SVI iteration for both hops. Warp per src node. One LDG.128 per edge.
__global__ void k_svi(int rb) {
    int g = blockIdx.x * blockDim.x + threadIdx.x;
    int w = g >> 5, lane = g & 31;
    if (w >= NN) return;
    int beg = g_rps[w], end = g_rps[w + 1];
    int wb = rb ^ 1;
    if (beg == end) {
        if (lane == 0) g_Vp[wb][w] = make_float2(0.f, 0.f);
        return;
    }
    float m0 = -INFINITY, s0 = 0.f, m1 = -INFINITY, s1 = 0.f;
    for (int p = beg + lane; p < end; p += 32) {
        int4 er = g_er[p];
        float2 V = g_Vp[rb][er.x];
        olse(m0, s0, __int_as_float(er.z) + V.x);
        olse(m1, s1, __int_as_float(er.w) + V.y);
    }
    wcomb(m0, s0);
    wcomb(m1, s1);
    if (lane == 0)
        g_Vp[wb][w] = make_float2(m0 + __logf(s0), m1 + __logf(s1));
}

// Final: logz & log_pi_obs lse, then per-node NLL + KL score. Warp per src node.
__global__ void k_finalize(float* __restrict__ outs, int write_score) {
    int g = blockIdx.x * blockDim.x + threadIdx.x;
    int w = g >> 5, lane = g & 31;
    if (w >= NN) return;
    int beg = g_rps[w], end = g_rps[w + 1];
    if (beg == end) {
        if (lane == 0 && write_score) outs[w] = 0.f;
        return;
    }
    float mq0 = -INFINITY, sq0 = 0.f, mq1 = -INFINITY, sq1 = 0.f;
    float mo0 = -INFINITY, so0 = 0.f, mo1 = -INFINITY, so1 = 0.f;
    float cq0 = 0.f, cq1 = 0.f, cl0 = 0.f, cl1 = 0.f;
    for (int p = beg + lane; p < end; p += 32) {
        int4 er = g_er[p];
        float2 V = g_Vp[1][er.x];
        float q0 = __int_as_float(er.z) + V.x;
        float q1 = __int_as_float(er.w) + V.y;
        float2 ac = g_ac[p];
        float l0 = __logf(ac.x + 1e-12f);
        float l1 = __logf(ac.y + 1e-12f);
        if (p - beg < 32) { cq0 = q0; cq1 = q1; cl0 = l0; cl1 = l1; }
        olse(mq0, sq0, q0); olse(mq1, sq1, q1);
        olse(mo0, so0, l0); olse(mo1, so1, l1);
    }
    wcomb(mq0, sq0); wcomb(mq1, sq1);
    wcomb(mo0, so0); wcomb(mo1, so1);
    float logz0 = mq0 + __logf(sq0), logz1 = mq1 + __logf(sq1);
    float lseo0 = mo0 + __logf(so0), lseo1 = mo1 + __logf(so1);
    float nll = 0.f, sc = 0.f;
    for (int p = beg + lane; p < end; p += 32) {
        float q0, q1, l0, l1;
        if (p - beg < 32) { q0 = cq0; q1 = cq1; l0 = cl0; l1 = cl1; }
        else {
            int4 er = g_er[p];
            float2 V = g_Vp[1][er.x];
            q0 = __int_as_float(er.z) + V.x;
            q1 = __int_as_float(er.w) + V.y;
            float2 ac = g_ac[p];
            l0 = __logf(ac.x + 1e-12f);
            l1 = __logf(ac.y + 1e-12f);
        }
        float lpo0 = l0 - lseo0, lps0 = q0 - logz0;
        float lpo1 = l1 - lseo1, lps1 = q1 - logz1;
        float p0 = __expf(lpo0), p1 = __expf(lpo1);
        nll += p0 * lps0 + p1 * lps1;
        sc  += p0 * (lpo0 - lps0) + p1 * (lpo1 - lps1);
    }
    nll = wsum(nll);
    sc  = wsum(sc);
    if (lane == 0) {
        if (write_score) outs[w] = sc;
        atomicAdd(&g_loss, -nll);
    }
}

__global__ void k_out(float* __restrict__ out) {
    if (threadIdx.x == 0 && blockIdx.x == 0) out[0] = g_loss / (float)NN;
}

// ---------------- host launcher ----------------
extern "C" void kernel_launch(void* const* d_in, const int* in_sizes, int n_in,
                              void* d_out, int out_size) {
    const float*     x   = (const float*)d_in[0];
    const void*      ei  = d_in[1];
    const float*     W0  = (const float*)d_in[2];
    const float*     as0 = (const float*)d_in[3];
    const float*     ad0 = (const float*)d_in[4];
    const float*     W1  = (const float*)d_in[5];
    const float*     as1 = (const float*)d_in[6];
    const float*     ad1 = (const float*)d_in[7];
    const float*     Ws1 = (const float*)d_in[8];
    const float*     bs1 = (const float*)d_in[9];
    const float*     ws2 = (const float*)d_in[10];
    const float*     bs2 = (const float*)d_in[11];
    const float*     Wm1 = (const float*)d_in[12];
    const float*     bm1 = (const float*)d_in[13];
    const float*     wm2 = (const float*)d_in[14];
    const float*     bm2 = (const float*)d_in[15];
    const float*     lam = (const float*)d_in[16];
    float* out = (float*)d_out;

    const int TB = 256;
    int bN   = (NN + TB - 1) / TB;
    int bE   = (NE + TB - 1) / TB;
    int bNW  = (NN * 32 + TB - 1) / TB;
    int bG   = (NN + 127) / 128;

    static cudaStream_t s1 = nullptr, s2 = nullptr;
    static cudaEvent_t eF0 = nullptr, eJ1 = nullptr, eF1 = nullptr, eJ2 = nullptr;
    if (!s1) {
        cudaStreamCreateWithFlags(&s1, cudaStreamNonBlocking);
        cudaStreamCreateWithFlags(&s2, cudaStreamNonBlocking);
        cudaEventCreateWithFlags(&eF0, cudaEventDisableTiming);
        cudaEventCreateWithFlags(&eJ1, cudaEventDisableTiming);
        cudaEventCreateWithFlags(&eF1, cudaEventDisableTiming);
        cudaEventCreateWithFlags(&eJ2, cudaEventDisableTiming);
    }
    cudaStream_t s0 = 0;

    // ---- fork s1: graph build, concurrent with x-GEMM on s0 ----
    cudaEventRecord(eF0, s0);
    cudaStreamWaitEvent(s1, eF0, 0);
    k_init<<<bN, TB, 0, s1>>>();
    k_detect<<<256, 256, 0, s1>>>((const int*)ei);
    k_tab<<<64, 256, 0, s1>>>(Ws1, bs1, ws2, bs2);
    k_prep<<<bE, TB, 0, s1>>>(ei);
    k_scan1<<<2 * NBLK, 256, 0, s1>>>();
    k_scan2<<<1, 512, 0, s1>>>();
    k_scan3<<<2 * NBLK, 256, 0, s1>>>();
    k_fill<<<bE, TB, 0, s1>>>();
    k_Wa<<<1, 128, 0, s1>>>(W1, as1, ad1);

    // s0: batched x-GEMM (P, U0, V0) + alP
    k_gemmB<<<dim3(bG, 3), TB, 0, s0>>>(x,
        0, 0, W0,             nullptr,
        1, 0, Wm1,            bm1,
        2, 0, Wm1 + 128 * HD, nullptr,
        NN);
    k_alP<<<bNW, TB, 0, s0>>>(as0, ad0);

    cudaEventRecord(eJ1, s1);
    cudaStreamWaitEvent(s0, eJ1, 0);

    k_gat1<<<bNW, TB, 0, s0>>>();

    // ---- fork s2: h1-GEMM, concurrent with al2/attn2 on s0 ----
    cudaEventRecord(eF1, s0);
    cudaStreamWaitEvent(s2, eF1, 0);
    k_gemmB<<<dim3(bG, 2), TB, 0, s2>>>(nullptr,
        1, 128, Wm1,            bm1,
        2, 128, Wm1 + 128 * HD, nullptr,
        0, 0,   Wm1,            nullptr,
        NN);

    k_al2<<<bNW, TB, 0, s0>>>();
    k_attn2<<<bNW, TB, 0, s0>>>();

    cudaEventRecord(eJ2, s2);
    cudaStreamWaitEvent(s0, eJ2, 0);

    k_rewards<<<bNW, TB, 0, s0>>>(wm2, bm2, lam, Ws1, bs1, ws2, bs2);
    for (int it = 1; it < 5; it++) k_svi<<<bNW, TB, 0, s0>>>(it & 1);

    if (out_size >= NN + 1) {
        k_finalize<<<bNW, TB, 0, s0>>>(out + 1, 1);
        k_out<<<1, 32, 0, s0>>>(out);
    } else if (out_size == NN) {
        k_finalize<<<bNW, TB, 0, s0>>>(out, 1);
    } else {
        k_finalize<<<bNW, TB, 0, s0>>>(out, 0);
        k_out<<<1, 32, 0, s0>>>(out);
    }
}

// round 16
// speedup vs baseline: 1.0398x; 1.0398x over previous
#include <cuda_runtime.h>
#include <cuda_pipeline.h>
#include <math.h>

#define NN 50000
#define NE 800000
#define HD 128
#define NH 8
#define NBLK 196   // ceil(NN/256)

typedef unsigned long long ull;

// ---------------- device scratch (static, no allocation) ----------------
__device__ float g_P[NN*HD];      // x @ W0 (layer-1 projection)
__device__ float g_h1[NN*HD];     // layer-1 output after elu
__device__ float g_TU[NN*256];    // [U0 | U1] per src node
__device__ float g_TV[NN*256];    // [V0 | V1] per dst node
__device__ float g_tab[128*128];  // structural reward lookup: 10*(ts(do,di)+bs2)
__device__ int   g_src[NE], g_dst[NE];
__device__ int   g_degout[NN], g_degin[NN];
__device__ int   g_rps[NN+1], g_rpd[NN+1];
__device__ int   g_curs[NN], g_curd[NN];
__device__ int   g_part[2][NBLK];
__device__ int2  g_adj2[NE];      // CSR order: (dst, float_bits(rstr10))
__device__ int2  g_csc[NE];       // CSC order: (csr_pos, src)
__device__ float g_als0[NN*NH], g_ald0[NN*NH], g_als1[NN*NH], g_ald1[NN*NH];
__device__ float g_Was[HD*NH], g_Wad[HD*NH];
__device__ float g_a1c[NE], g_a2c[NE];   // attention in CSR order
__device__ float2 g_rr[NE];              // (10*r0, 10*r1) in CSR order
__device__ float2 g_Vp[2][NN];           // V*10 packed (hop0,hop1), double-buffered
__device__ float g_loss;
__device__ int   g_is64;

__device__ __forceinline__ float* sel_node(int s) {
    switch (s) { case 0: return g_P; case 1: return g_TU; default: return g_TV; }
}

// ---------------- f32x2 packed math helpers (Blackwell) ----------------
__device__ __forceinline__ ull packf2(float lo, float hi) {
    ull r;
    asm("mov.b64 %0, {%1, %2};" : "=l"(r) : "f"(lo), "f"(hi));
    return r;
}
__device__ __forceinline__ void unpackf2(ull v, float& lo, float& hi) {
    asm("mov.b64 {%0, %1}, %2;" : "=f"(lo), "=f"(hi) : "l"(v));
}
__device__ __forceinline__ void fmaf2(ull& d, ull a, ull b) {
    asm("fma.rn.f32x2 %0, %1, %2, %0;" : "+l"(d) : "l"(a), "l"(b));
}

// ---------------- helpers ----------------
__device__ __forceinline__ void olse(float& m, float& s, float q) {
    if (q > m) { s = s * __expf(m - q) + 1.f; m = q; }
    else       { s += __expf(q - m); }
}
__device__ __forceinline__ void wcomb(float& m, float& s) {
    #pragma unroll
    for (int off = 16; off; off >>= 1) {
        float mo = __shfl_xor_sync(0xffffffffu, m, off);
        float so = __shfl_xor_sync(0xffffffffu, s, off);
        float M  = fmaxf(m, mo);
        float ea = (m  == M) ? 1.f : __expf(m  - M);
        float eb = (mo == M) ? 1.f : __expf(mo - M);
        s = s * ea + so * eb; m = M;
    }
}
// 16-lane-group variants (offsets 8..1 stay within a half-warp)
__device__ __forceinline__ void wcomb16(float& m, float& s) {
    #pragma unroll
    for (int off = 8; off; off >>= 1) {
        float mo = __shfl_xor_sync(0xffffffffu, m, off);
        float so = __shfl_xor_sync(0xffffffffu, s, off);
        float M  = fmaxf(m, mo);
        float ea = (m  == M) ? 1.f : __expf(m  - M);
        float eb = (mo == M) ? 1.f : __expf(mo - M);
        s = s * ea + so * eb; m = M;
    }
}
__device__ __forceinline__ float wsum(float v) {
    #pragma unroll
    for (int off = 16; off; off >>= 1) v += __shfl_xor_sync(0xffffffffu, v, off);
    return v;
}
__device__ __forceinline__ float wsum16(float v) {
    #pragma unroll
    for (int off = 8; off; off >>= 1) v += __shfl_xor_sync(0xffffffffu, v, off);
    return v;
}
__device__ __forceinline__ int wsumi(int v) {
    #pragma unroll
    for (int off = 16; off; off >>= 1) v += __shfl_xor_sync(0xffffffffu, v, off);
    return v;
}

// ---------------- kernels ----------------
__global__ void k_init() {
    int i = blockIdx.x * blockDim.x + threadIdx.x;
    if (i < NN) { g_degout[i] = 0; g_degin[i] = 0; }
    if (i == 0) { g_loss = 0.f; g_is64 = 1; }
}

__global__ void k_detect(const int* __restrict__ ei32) {
    int i = blockIdx.x * blockDim.x + threadIdx.x;
    if (i < 65536) {
        if (ei32[2 * i + 1] != 0) g_is64 = 0;
    }
}

// Structural reward lookup table: tab[do][di] = 10*(mlp2([do,di,log1p,log1p])+bs2)
__global__ void k_tab(const float* __restrict__ Ws1, const float* __restrict__ bs1,
                      const float* __restrict__ ws2, const float* __restrict__ b2s) {
    int gw = (int)((blockIdx.x * blockDim.x + threadIdx.x) >> 5);
    int lane = threadIdx.x & 31;
    int nw = (int)((gridDim.x * blockDim.x) >> 5);
    float w1[4], w2[4], w3[4], w4[4], bb[4], wk[4];
    #pragma unroll
    for (int j = 0; j < 4; j++) {
        int k = lane * 4 + j;
        w1[j] = Ws1[k]; w2[j] = Ws1[128 + k]; w3[j] = Ws1[256 + k]; w4[j] = Ws1[384 + k];
        bb[j] = bs1[k]; wk[j] = ws2[k];
    }
    float b2v = *b2s;
    for (int e = gw; e < 128 * 128; e += nw) {
        int dO = e >> 7, dI = e & 127;
        float fo = (float)dO, fi = (float)dI;
        float lo = log1pf(fo), li = log1pf(fi);
        float t = 0.f;
        #pragma unroll
        for (int j = 0; j < 4; j++) {
            float us = fo * w1[j] + lo * w3[j] + bb[j];
            float vs = fi * w2[j] + li * w4[j];
            t += fmaxf(us + vs, 0.f) * wk[j];
        }
        t = wsum(t);
        if (lane == 0) g_tab[e] = 10.f * (t + b2v);
    }
}

__global__ void k_prep(const void* __restrict__ eiv) {
    int e = blockIdx.x * blockDim.x + threadIdx.x;
    if (e >= NE) return;
    int s, d;
    if (g_is64) {
        const long long* ei = (const long long*)eiv;
        s = (int)ei[e]; d = (int)ei[NE + e];
    } else {
        const int* ei = (const int*)eiv;
        s = ei[e]; d = ei[NE + e];
    }
    s = min(max(s, 0), NN - 1);
    d = min(max(d, 0), NN - 1);
    g_src[e] = s; g_dst[e] = d;
    atomicAdd(&g_degout[s], 1);
    atomicAdd(&g_degin[d], 1);
}

__global__ void k_scan1() {
    int a = blockIdx.x >= NBLK;
    int b = blockIdx.x - a * NBLK;
    const int* deg = a ? g_degin : g_degout;
    int i = b * 256 + threadIdx.x;
    int v = (i < NN) ? deg[i] : 0;
    __shared__ int sw[8];
    int ws = wsumi(v);
    if ((threadIdx.x & 31) == 0) sw[threadIdx.x >> 5] = ws;
    __syncthreads();
    if (threadIdx.x == 0) {
        int t = 0;
        #pragma unroll
        for (int j = 0; j < 8; j++) t += sw[j];
        g_part[a][b] = t;
    }
}

__global__ void k_scan2() {
    int a = threadIdx.x >> 8;
    int t = threadIdx.x & 255;
    __shared__ int sh[2][256];
    int v = (t < NBLK) ? g_part[a][t] : 0;
    sh[a][t] = v;
    __syncthreads();
    for (int off = 1; off < 256; off <<= 1) {
        int u = (t >= off) ? sh[a][t - off] : 0;
        __syncthreads();
        sh[a][t] += u;
        __syncthreads();
    }
    if (t < NBLK) g_part[a][t] = sh[a][t] - v;
    if (t == 255) {
        if (a) g_rpd[NN] = sh[1][255]; else g_rps[NN] = sh[0][255];
    }
}

__global__ void k_scan3() {
    int a = blockIdx.x >= NBLK;
    int b = blockIdx.x - a * NBLK;
    const int* deg = a ? g_degin : g_degout;
    int* rp  = a ? g_rpd  : g_rps;
    int* cur = a ? g_curd : g_curs;
    int i = b * 256 + threadIdx.x;
    int v = (i < NN) ? deg[i] : 0;
    __shared__ int sh[256];
    sh[threadIdx.x] = v;
    __syncthreads();
    for (int off = 1; off < 256; off <<= 1) {
        int u = (threadIdx.x >= off) ? sh[threadIdx.x - off] : 0;
        __syncthreads();
        sh[threadIdx.x] += u;
        __syncthreads();
    }
    if (i < NN) {
        int excl = sh[threadIdx.x] - v + g_part[a][b];
        rp[i] = excl; cur[i] = excl;
    }
}

__global__ void k_fill() {
    int e = blockIdx.x * blockDim.x + threadIdx.x;
    if (e >= NE) return;
    int s = g_src[e], d = g_dst[e];
    int dO = g_degout[s], dI = g_degin[d];
    float r = (dO < 128 && dI < 128) ? g_tab[dO * 128 + dI]
                                     : __int_as_float(0x7fc00000);  // NaN sentinel
    int p = atomicAdd(&g_curs[s], 1);
    g_adj2[p] = make_int2(d, __float_as_int(r));
    int q = atomicAdd(&g_curd[d], 1);
    g_csc[q] = make_int2(p, s);
}

// Batched GEMM: up to 3 (dsel,coff,B,bias) configs selected by blockIdx.y,
// sharing A. 128x128 tile, 8x8 micro via fma.rn.f32x2. Double-buffered smem:
// B tiles via cp.async, A tiles prefetched one tile ahead.
__global__ void __launch_bounds__(256, 2) k_gemmB(
        const float* __restrict__ aext,
        int d0, int c0, const float* __restrict__ B0, const float* __restrict__ bias0,
        int d1, int c1, const float* __restrict__ B1, const float* __restrict__ bias1,
        int d2, int c2, const float* __restrict__ B2, const float* __restrict__ bias2,
        int M) {
    const float* A = aext ? aext : g_h1;
    int dsel, coff;
    const float *B, *bias;
    if (blockIdx.y == 0)      { dsel = d0; coff = c0; B = B0; bias = bias0; }
    else if (blockIdx.y == 1) { dsel = d1; coff = c1; B = B1; bias = bias1; }
    else                      { dsel = d2; coff = c2; B = B2; bias = bias2; }
    float* C = sel_node(dsel);
    int cs = (dsel == 0) ? 128 : 256;
    __shared__ float Ast[2][16][136];
    __shared__ float Bs[2][16][128];
    int bm = blockIdx.x * 128;
    int tid = threadIdx.x;
    int tr = tid >> 4, tc = tid & 15;
    int ar = tid >> 2, ac = (tid & 3) << 2;
    int br = tid >> 5, bc = (tid & 31) << 2;
    ull acc[8][4];
    #pragma unroll
    for (int i = 0; i < 8; i++)
        #pragma unroll
        for (int j = 0; j < 4; j++) acc[i][j] = 0ull;

    float4 pa0, pa1;

    {
        float4 v0 = make_float4(0.f, 0.f, 0.f, 0.f), v1 = v0;
        if (bm + ar < M)       v0 = *(const float4*)&A[(size_t)(bm + ar) * HD + ac];
        if (bm + ar + 64 < M)  v1 = *(const float4*)&A[(size_t)(bm + ar + 64) * HD + ac];
        Ast[0][ac][ar] = v0.x; Ast[0][ac+1][ar] = v0.y; Ast[0][ac+2][ar] = v0.z; Ast[0][ac+3][ar] = v0.w;
        Ast[0][ac][ar+64] = v1.x; Ast[0][ac+1][ar+64] = v1.y; Ast[0][ac+2][ar+64] = v1.z; Ast[0][ac+3][ar+64] = v1.w;
        __pipeline_memcpy_async(&Bs[0][br][bc],     &B[(size_t)br * HD + bc], 16);
        __pipeline_memcpy_async(&Bs[0][br + 8][bc], &B[(size_t)(br + 8) * HD + bc], 16);
        __pipeline_commit();
        __pipeline_wait_prior(0);
        pa0 = make_float4(0.f, 0.f, 0.f, 0.f); pa1 = pa0;
        if (bm + ar < M)       pa0 = *(const float4*)&A[(size_t)(bm + ar) * HD + 16 + ac];
        if (bm + ar + 64 < M)  pa1 = *(const float4*)&A[(size_t)(bm + ar + 64) * HD + 16 + ac];
        __pipeline_memcpy_async(&Bs[1][br][bc],     &B[(size_t)(16 + br) * HD + bc], 16);
        __pipeline_memcpy_async(&Bs[1][br + 8][bc], &B[(size_t)(16 + br + 8) * HD + bc], 16);
        __pipeline_commit();
        __syncthreads();
    }

    #pragma unroll 1
    for (int t = 0; t < 8; t++) {
        int cur = t & 1;
        #pragma unroll
        for (int k = 0; k < 16; k++) {
            float4 a0 = *(float4*)&Ast[cur][k][tr * 8];
            float4 a1 = *(float4*)&Ast[cur][k][tr * 8 + 4];
            float4 b0 = *(float4*)&Bs[cur][k][tc * 8];
            float4 b1 = *(float4*)&Bs[cur][k][tc * 8 + 4];
            ull b2[4] = { packf2(b0.x, b0.y), packf2(b0.z, b0.w),
                          packf2(b1.x, b1.y), packf2(b1.z, b1.w) };
            float av[8] = {a0.x, a0.y, a0.z, a0.w, a1.x, a1.y, a1.z, a1.w};
            #pragma unroll
            for (int i = 0; i < 8; i++) {
                ull af = packf2(av[i], av[i]);
                #pragma unroll
                for (int j = 0; j < 4; j++) fmaf2(acc[i][j], af, b2[j]);
            }
        }
        if (t < 7) {
            int nxt = cur ^ 1;
            __syncthreads();
            Ast[nxt][ac][ar] = pa0.x; Ast[nxt][ac+1][ar] = pa0.y;
            Ast[nxt][ac+2][ar] = pa0.z; Ast[nxt][ac+3][ar] = pa0.w;
            Ast[nxt][ac][ar+64] = pa1.x; Ast[nxt][ac+1][ar+64] = pa1.y;
            Ast[nxt][ac+2][ar+64] = pa1.z; Ast[nxt][ac+3][ar+64] = pa1.w;
            __pipeline_wait_prior(0);
            if (t < 6) {
                int k0 = (t + 2) * 16;
                pa0 = make_float4(0.f, 0.f, 0.f, 0.f); pa1 = pa0;
                if (bm + ar < M)      pa0 = *(const float4*)&A[(size_t)(bm + ar) * HD + k0 + ac];
                if (bm + ar + 64 < M) pa1 = *(const float4*)&A[(size_t)(bm + ar + 64) * HD + k0 + ac];
                __pipeline_memcpy_async(&Bs[cur][br][bc],     &B[(size_t)(k0 + br) * HD + bc], 16);
                __pipeline_memcpy_async(&Bs[cur][br + 8][bc], &B[(size_t)(k0 + br + 8) * HD + bc], 16);
                __pipeline_commit();
            }
            __syncthreads();
        }
    }
    #pragma unroll
    for (int i = 0; i < 8; i++) {
        int row = bm + tr * 8 + i;
        if (row < M) {
            #pragma unroll
            for (int j = 0; j < 4; j++) {
                float lo, hi;
                unpackf2(acc[i][j], lo, hi);
                int col = tc * 8 + j * 2;
                if (bias) { lo += bias[col]; hi += bias[col + 1]; }
                C[(size_t)row * cs + coff + col]     = lo;
                C[(size_t)row * cs + coff + col + 1] = hi;
            }
        }
    }
}

// al_s0/al_d0 from P (warp per node)
__global__ void k_alP(const float* __restrict__ as0, const float* __restrict__ ad0) {
    int g = blockIdx.x * blockDim.x + threadIdx.x;
    int w = g >> 5, lane = g & 31;
    if (w >= NN) return;
    int h = lane >> 2;
    int off = (lane & 3) * 4;
    float4 v = *(const float4*)&g_P[(size_t)w * HD + lane * 4];
    const float* a = &as0[h * 16 + off];
    const float* b = &ad0[h * 16 + off];
    float ps = v.x * a[0] + v.y * a[1] + v.z * a[2] + v.w * a[3];
    float pd = v.x * b[0] + v.y * b[1] + v.z * b[2] + v.w * b[3];
    ps += __shfl_xor_sync(0xffffffffu, ps, 1);
    ps += __shfl_xor_sync(0xffffffffu, ps, 2);
    pd += __shfl_xor_sync(0xffffffffu, pd, 1);
    pd += __shfl_xor_sync(0xffffffffu, pd, 2);
    if ((lane & 3) == 0) { g_als0[w * NH + h] = ps; g_ald0[w * NH + h] = pd; }
}

// GAT layer 1: softmax over incoming edges + aggregation + elu. Warp per dst node.
__global__ void __launch_bounds__(256) k_gat1() {
    __shared__ float s_at[8][256];
    __shared__ int   s_sc[8][32];
    int g = blockIdx.x * blockDim.x + threadIdx.x;
    int w = g >> 5, lane = g & 31, wl = threadIdx.x >> 5;
    if (w >= NN) return;
    int beg = g_rpd[w], end = g_rpd[w + 1];
    float ald[8];
    #pragma unroll
    for (int h = 0; h < 8; h++) ald[h] = g_ald0[w * NH + h];
    float m[8], s[8], ec[8];
    #pragma unroll
    for (int h = 0; h < 8; h++) { m[h] = -INFINITY; s[h] = 0.f; ec[h] = 0.f; }
    for (int p = beg + lane; p < end; p += 32) {
        int sn = g_csc[p].y;
        const float4* ap = (const float4*)&g_als0[sn * NH];
        float4 a0 = ap[0], a1 = ap[1];
        float ev[8] = {a0.x, a0.y, a0.z, a0.w, a1.x, a1.y, a1.z, a1.w};
        #pragma unroll
        for (int h = 0; h < 8; h++) {
            float e = ev[h] + ald[h];
            e = (e > 0.f) ? e : 0.2f * e;
            if (p - beg < 32) ec[h] = e;
            olse(m[h], s[h], e);
        }
    }
    #pragma unroll
    for (int h = 0; h < 8; h++) wcomb(m[h], s[h]);
    float lse[8];
    #pragma unroll
    for (int h = 0; h < 8; h++) lse[h] = m[h] + __logf(s[h]);

    ull accp0 = 0ull, accp1 = 0ull;
    int h0 = lane >> 2;
    for (int t0 = beg; t0 < end; t0 += 32) {
        int p = t0 + lane;
        int cnt = min(32, end - t0);
        if (p < end) {
            int2 cs = g_csc[p];
            int sn = cs.y;
            float ev[8];
            if (t0 == beg) {
                #pragma unroll
                for (int h = 0; h < 8; h++) ev[h] = ec[h];
            } else {
                const float4* ap = (const float4*)&g_als0[sn * NH];
                float4 a0 = ap[0], a1 = ap[1];
                float tv[8] = {a0.x, a0.y, a0.z, a0.w, a1.x, a1.y, a1.z, a1.w};
                #pragma unroll
                for (int h = 0; h < 8; h++) {
                    float e = tv[h] + ald[h];
                    ev[h] = (e > 0.f) ? e : 0.2f * e;
                }
            }
            float asum = 0.f;
            #pragma unroll
            for (int h = 0; h < 8; h++) {
                float a = __expf(ev[h] - lse[h]);
                s_at[wl][lane * 8 + h] = a;
                asum += a;
            }
            g_a1c[cs.x] = asum * 0.125f;
            s_sc[wl][lane] = sn;
        }
        __syncwarp();
        for (int j = 0; j < cnt; j++) {
            int sj = s_sc[wl][j];
            float a = s_at[wl][j * 8 + h0];
            float4 pv = *(const float4*)&g_P[(size_t)sj * HD + lane * 4];
            ull af = packf2(a, a);
            fmaf2(accp0, af, packf2(pv.x, pv.y));
            fmaf2(accp1, af, packf2(pv.z, pv.w));
        }
        __syncwarp();
    }
    float4 hv;
    unpackf2(accp0, hv.x, hv.y);
    unpackf2(accp1, hv.z, hv.w);
    hv.x = (hv.x > 0.f) ? hv.x : expm1f(hv.x);
    hv.y = (hv.y > 0.f) ? hv.y : expm1f(hv.y);
    hv.z = (hv.z > 0.f) ? hv.z : expm1f(hv.z);
    hv.w = (hv.w > 0.f) ? hv.w : expm1f(hv.w);
    *(float4*)&g_h1[(size_t)w * HD + lane * 4] = hv;
}

// Fold W1 with per-head attention vectors
__global__ void k_Wa(const float* __restrict__ W1, const float* __restrict__ as1,
                     const float* __restrict__ ad1) {
    int k = threadIdx.x;
    #pragma unroll
    for (int h = 0; h < 8; h++) {
        float ss = 0.f, sd = 0.f;
        #pragma unroll
        for (int d = 0; d < 16; d++) {
            float wv = W1[k * HD + h * 16 + d];
            ss += wv * as1[h * 16 + d];
            sd += wv * ad1[h * 16 + d];
        }
        g_Was[k * 8 + h] = ss;
        g_Wad[k * 8 + h] = sd;
    }
}

// al_s1/al_d1 = h1 @ Wa (warp per node)
__global__ void k_al2() {
    int g = blockIdx.x * blockDim.x + threadIdx.x;
    int w = g >> 5, lane = g & 31;
    if (w >= NN) return;
    float4 v = *(const float4*)&g_h1[(size_t)w * HD + lane * 4];
    float xv[4] = {v.x, v.y, v.z, v.w};
    float ps[8], pd[8];
    #pragma unroll
    for (int h = 0; h < 8; h++) { ps[h] = 0.f; pd[h] = 0.f; }
    #pragma unroll
    for (int j = 0; j < 4; j++) {
        int k = lane * 4 + j;
        const float* was = &g_Was[k * 8];
        const float* wad = &g_Wad[k * 8];
        #pragma unroll
        for (int h = 0; h < 8; h++) {
            ps[h] = fmaf(xv[j], was[h], ps[h]);
            pd[h] = fmaf(xv[j], wad[h], pd[h]);
        }
    }
    #pragma unroll
    for (int off = 16; off; off >>= 1)
        #pragma unroll
        for (int h = 0; h < 8; h++) {
            ps[h] += __shfl_xor_sync(0xffffffffu, ps[h], off);
            pd[h] += __shfl_xor_sync(0xffffffffu, pd[h], off);
        }
    if (lane == 0) {
        #pragma unroll
        for (int h = 0; h < 8; h++) {
            g_als1[w * NH + h] = ps[h];
            g_ald1[w * NH + h] = pd[h];
        }
    }
}

// Layer-2 attention only (a2). Warp per dst node; float4x2 gathers.
__global__ void k_attn2() {
    int g = blockIdx.x * blockDim.x + threadIdx.x;
    int w = g >> 5, lane = g & 31;
    if (w >= NN) return;
    int beg = g_rpd[w], end = g_rpd[w + 1];
    if (beg == end) return;
    float ald[8];
    #pragma unroll
    for (int h = 0; h < 8; h++) ald[h] = g_ald1[w * NH + h];
    float m[8], s[8], ec[8];
    #pragma unroll
    for (int h = 0; h < 8; h++) { m[h] = -INFINITY; s[h] = 0.f; ec[h] = 0.f; }
    for (int p = beg + lane; p < end; p += 32) {
        int sn = g_csc[p].y;
        const float4* ap = (const float4*)&g_als1[sn * NH];
        float4 a0 = ap[0], a1 = ap[1];
        float ev[8] = {a0.x, a0.y, a0.z, a0.w, a1.x, a1.y, a1.z, a1.w};
        #pragma unroll
        for (int h = 0; h < 8; h++) {
            float e = ev[h] + ald[h];
            e = (e > 0.f) ? e : 0.2f * e;
            if (p - beg < 32) ec[h] = e;
            olse(m[h], s[h], e);
        }
    }
    #pragma unroll
    for (int h = 0; h < 8; h++) wcomb(m[h], s[h]);
    float lse[8];
    #pragma unroll
    for (int h = 0; h < 8; h++) lse[h] = m[h] + __logf(s[h]);
    for (int p = beg + lane; p < end; p += 32) {
        int2 cs = g_csc[p];
        float asum = 0.f;
        if (p - beg < 32) {
            #pragma unroll
            for (int h = 0; h < 8; h++) asum += __expf(ec[h] - lse[h]);
        } else {
            int sn = cs.y;
            const float4* ap = (const float4*)&g_als1[sn * NH];
            float4 a0 = ap[0], a1 = ap[1];
            float ev[8] = {a0.x, a0.y, a0.z, a0.w, a1.x, a1.y, a1.z, a1.w};
            #pragma unroll
            for (int h = 0; h < 8; h++) {
                float e = ev[h] + ald[h];
                e = (e > 0.f) ? e : 0.2f * e;
                asum += __expf(e - lse[h]);
            }
        }
        g_a2c[cs.x] = asum * 0.125f;
    }
}

// Fused semantic reward kernel + SVI iteration 0 (V0=0 => Q=r => V1=lse(r)).
__global__ void __launch_bounds__(256) k_rewards(const float* __restrict__ w2m,
                                                 const float* __restrict__ b2m,
                                                 const float* __restrict__ lam,
                                                 const float* __restrict__ Ws1,
                                                 const float* __restrict__ bs1,
                                                 const float* __restrict__ ws2,
                                                 const float* __restrict__ b2s) {
    int g = blockIdx.x * blockDim.x + threadIdx.x;
    int w = g >> 5, lane = g & 31;
    if (w >= NN) return;
    int beg = g_rps[w], end = g_rps[w + 1];
    if (beg == end) {
        if (lane == 0) g_Vp[1][w] = make_float2(0.f, 0.f);
        return;
    }
    size_t ro = (size_t)w * 256 + lane * 4;
    float4 u0 = *(const float4*)&g_TU[ro];
    float4 u1 = *(const float4*)&g_TU[ro + 128];
    float4 wm = *(const float4*)&w2m[lane * 4];
    float bm2v = *b2m, lam10 = 10.f * (*lam);
    float m0 = -INFINITY, s0 = 0.f, m1 = -INFINITY, s1 = 0.f;
    for (int p = beg; p < end; p++) {
        int2 ad = g_adj2[p];
        int d = ad.x;
        float rstr10 = __int_as_float(ad.y);
        size_t co = (size_t)d * 256 + lane * 4;
        float4 v0 = *(const float4*)&g_TV[co];
        float4 v1 = *(const float4*)&g_TV[co + 128];
        float t0 = fmaxf(u0.x + v0.x, 0.f) * wm.x + fmaxf(u0.y + v0.y, 0.f) * wm.y +
                   fmaxf(u0.z + v0.z, 0.f) * wm.z + fmaxf(u0.w + v0.w, 0.f) * wm.w;
        float t1 = fmaxf(u1.x + v1.x, 0.f) * wm.x + fmaxf(u1.y + v1.y, 0.f) * wm.y +
                   fmaxf(u1.z + v1.z, 0.f) * wm.z + fmaxf(u1.w + v1.w, 0.f) * wm.w;
        #pragma unroll
        for (int off = 16; off; off >>= 1) {
            t0 += __shfl_xor_sync(0xffffffffu, t0, off);
            t1 += __shfl_xor_sync(0xffffffffu, t1, off);
        }
        if (!(rstr10 == rstr10)) {
            float fo = (float)g_degout[w], fi = (float)g_degin[d];
            float lo = log1pf(fo), li = log1pf(fi);
            float ts = 0.f;
            #pragma unroll
            for (int j = 0; j < 4; j++) {
                int k = lane * 4 + j;
                float us = fo * Ws1[k] + lo * Ws1[256 + k] + bs1[k];
                float vs = fi * Ws1[128 + k] + li * Ws1[384 + k];
                ts += fmaxf(us + vs, 0.f) * ws2[k];
            }
            ts = wsum(ts);
            rstr10 = 10.f * (ts + *b2s);
        }
        float r0 = rstr10 + lam10 * (t0 + bm2v);
        float r1 = rstr10 + lam10 * (t1 + bm2v);
        if (lane == 0) g_rr[p] = make_float2(r0, r1);
        olse(m0, s0, r0);
        olse(m1, s1, r1);
    }
    if (lane == 0)
        g_Vp[1][w] = make_float2(m0 + __logf(s0), m1 + __logf(s1));
}

// One SVI iteration for both hops. HALF-WARP (16 lanes) per src node
// (mean degree = 16, so a full warp leaves half the lanes idle).
__global__ void k_svi(int rb) {
    int g = blockIdx.x * blockDim.x + threadIdx.x;
    int w = g >> 4, lane = g & 15;
    if (w >= NN) return;
    int beg = g_rps[w], end = g_rps[w + 1];
    int wb = rb ^ 1;
    if (beg == end) {
        if (lane == 0) g_Vp[wb][w] = make_float2(0.f, 0.f);
        return;
    }
    float m0 = -INFINITY, s0 = 0.f, m1 = -INFINITY, s1 = 0.f;
    for (int p = beg + lane; p < end; p += 16) {
        float2 r = g_rr[p];
        float2 V = g_Vp[rb][g_adj2[p].x];
        olse(m0, s0, r.x + V.x);
        olse(m1, s1, r.y + V.y);
    }
    wcomb16(m0, s0);
    wcomb16(m1, s1);
    if (lane == 0)
        g_Vp[wb][w] = make_float2(m0 + __logf(s0), m1 + __logf(s1));
}

// Final: logz & log_pi_obs lse, then per-node NLL + KL score.
// HALF-WARP (16 lanes) per src node.
__global__ void k_finalize(float* __restrict__ outs, int write_score) {
    int g = blockIdx.x * blockDim.x + threadIdx.x;
    int w = g >> 4, lane = g & 15;
    if (w >= NN) return;
    int beg = g_rps[w], end = g_rps[w + 1];
    if (beg == end) {
        if (lane == 0 && write_score) outs[w] = 0.f;
        return;
    }
    float mq0 = -INFINITY, sq0 = 0.f, mq1 = -INFINITY, sq1 = 0.f;
    float mo0 = -INFINITY, so0 = 0.f, mo1 = -INFINITY, so1 = 0.f;
    float cq0 = 0.f, cq1 = 0.f, cl0 = 0.f, cl1 = 0.f;
    for (int p = beg + lane; p < end; p += 16) {
        float2 r = g_rr[p];
        float2 V = g_Vp[1][g_adj2[p].x];
        float q0 = r.x + V.x;
        float q1 = r.y + V.y;
        float l0 = __logf(g_a1c[p] + 1e-12f);
        float l1 = __logf(g_a2c[p] + 1e-12f);
        if (p - beg < 16) { cq0 = q0; cq1 = q1; cl0 = l0; cl1 = l1; }
        olse(mq0, sq0, q0); olse(mq1, sq1, q1);
        olse(mo0, so0, l0); olse(mo1, so1, l1);
    }
    wcomb16(mq0, sq0); wcomb16(mq1, sq1);
    wcomb16(mo0, so0); wcomb16(mo1, so1);
    float logz0 = mq0 + __logf(sq0), logz1 = mq1 + __logf(sq1);
    float lseo0 = mo0 + __logf(so0), lseo1 = mo1 + __logf(so1);
    float nll = 0.f, sc = 0.f;
    for (int p = beg + lane; p < end; p += 16) {
        float q0, q1, l0, l1;
        if (p - beg < 16) { q0 = cq0; q1 = cq1; l0 = cl0; l1 = cl1; }
        else {
            float2 r = g_rr[p];
            float2 V = g_Vp[1][g_adj2[p].x];
            q0 = r.x + V.x;
            q1 = r.y + V.y;
            l0 = __logf(g_a1c[p] + 1e-12f);
            l1 = __logf(g_a2c[p] + 1e-12f);
        }
        float lpo0 = l0 - lseo0, lps0 = q0 - logz0;
        float lpo1 = l1 - lseo1, lps1 = q1 - logz1;
        float p0 = __expf(lpo0), p1 = __expf(lpo1);
        nll += p0 * lps0 + p1 * lps1;
        sc  += p0 * (lpo0 - lps0) + p1 * (lpo1 - lps1);
    }
    nll = wsum16(nll);
    sc  = wsum16(sc);
    if (lane == 0) {
        if (write_score) outs[w] = sc;
        atomicAdd(&g_loss, -nll);
    }
}

__global__ void k_out(float* __restrict__ out) {
    if (threadIdx.x == 0 && blockIdx.x == 0) out[0] = g_loss / (float)NN;
}

// ---------------- host launcher ----------------
extern "C" void kernel_launch(void* const* d_in, const int* in_sizes, int n_in,
                              void* d_out, int out_size) {
    const float*     x   = (const float*)d_in[0];
    const void*      ei  = d_in[1];
    const float*     W0  = (const float*)d_in[2];
    const float*     as0 = (const float*)d_in[3];
    const float*     ad0 = (const float*)d_in[4];
    const float*     W1  = (const float*)d_in[5];
    const float*     as1 = (const float*)d_in[6];
    const float*     ad1 = (const float*)d_in[7];
    const float*     Ws1 = (const float*)d_in[8];
    const float*     bs1 = (const float*)d_in[9];
    const float*     ws2 = (const float*)d_in[10];
    const float*     bs2 = (const float*)d_in[11];
    const float*     Wm1 = (const float*)d_in[12];
    const float*     bm1 = (const float*)d_in[13];
    const float*     wm2 = (const float*)d_in[14];
    const float*     bm2 = (const float*)d_in[15];
    const float*     lam = (const float*)d_in[16];
    float* out = (float*)d_out;

    const int TB = 256;
    int bN    = (NN + TB - 1) / TB;
    int bE    = (NE + TB - 1) / TB;
    int bNW   = (NN * 32 + TB - 1) / TB;   // warp-per-node
    int bNW16 = (NN * 16 + TB - 1) / TB;   // half-warp-per-node
    int bG    = (NN + 127) / 128;

    static cudaStream_t s1 = nullptr, s2 = nullptr;
    static cudaEvent_t eF0 = nullptr, eJ1 = nullptr, eF1 = nullptr, eJ2 = nullptr;
    if (!s1) {
        cudaStreamCreateWithFlags(&s1, cudaStreamNonBlocking);
        cudaStreamCreateWithFlags(&s2, cudaStreamNonBlocking);
        cudaEventCreateWithFlags(&eF0, cudaEventDisableTiming);
        cudaEventCreateWithFlags(&eJ1, cudaEventDisableTiming);
        cudaEventCreateWithFlags(&eF1, cudaEventDisableTiming);
        cudaEventCreateWithFlags(&eJ2, cudaEventDisableTiming);
    }
    cudaStream_t s0 = 0;

    // ---- fork s1: graph build, concurrent with x-GEMM on s0 ----
    cudaEventRecord(eF0, s0);
    cudaStreamWaitEvent(s1, eF0, 0);
    k_init<<<bN, TB, 0, s1>>>();
    k_detect<<<256, 256, 0, s1>>>((const int*)ei);
    k_tab<<<64, 256, 0, s1>>>(Ws1, bs1, ws2, bs2);
    k_prep<<<bE, TB, 0, s1>>>(ei);
    k_scan1<<<2 * NBLK, 256, 0, s1>>>();
    k_scan2<<<1, 512, 0, s1>>>();
    k_scan3<<<2 * NBLK, 256, 0, s1>>>();
    k_fill<<<bE, TB, 0, s1>>>();
    k_Wa<<<1, 128, 0, s1>>>(W1, as1, ad1);

    // s0: batched x-GEMM (P, U0, V0) + alP
    k_gemmB<<<dim3(bG, 3), TB, 0, s0>>>(x,
        0, 0, W0,             nullptr,
        1, 0, Wm1,            bm1,
        2, 0, Wm1 + 128 * HD, nullptr,
        NN);
    k_alP<<<bNW, TB, 0, s0>>>(as0, ad0);

    cudaEventRecord(eJ1, s1);
    cudaStreamWaitEvent(s0, eJ1, 0);

    k_gat1<<<bNW, TB, 0, s0>>>();

    // ---- fork s2: h1-GEMM, concurrent with al2/attn2 on s0 ----
    cudaEventRecord(eF1, s0);
    cudaStreamWaitEvent(s2, eF1, 0);
    k_gemmB<<<dim3(bG, 2), TB, 0, s2>>>(nullptr,
        1, 128, Wm1,            bm1,
        2, 128, Wm1 + 128 * HD, nullptr,
        0, 0,   Wm1,            nullptr,
        NN);

    k_al2<<<bNW, TB, 0, s0>>>();
    k_attn2<<<bNW, TB, 0, s0>>>();

    cudaEventRecord(eJ2, s2);
    cudaStreamWaitEvent(s0, eJ2, 0);

    k_rewards<<<bNW, TB, 0, s0>>>(wm2, bm2, lam, Ws1, bs1, ws2, bs2);
    for (int it = 1; it < 5; it++) k_svi<<<bNW16, TB, 0, s0>>>(it & 1);

    if (out_size >= NN + 1) {
        k_finalize<<<bNW16, TB, 0, s0>>>(out + 1, 1);
        k_out<<<1, 32, 0, s0>>>(out);
    } else if (out_size == NN) {
        k_finalize<<<bNW16, TB, 0, s0>>>(out, 1);
    } else {
        k_finalize<<<bNW16, TB, 0, s0>>>(out, 0);
        k_out<<<1, 32, 0, s0>>>(out);
    }
}

// round 17
// speedup vs baseline: 1.0804x; 1.0391x over previous
#include <cuda_runtime.h>
#include <cuda_pipeline.h>
#include <math.h>

#define NN 50000
#define NE 800000
#define HD 128
#define NH 8
#define NBLK 196   // ceil(NN/256)

typedef unsigned long long ull;

// ---------------- device scratch (static, no allocation) ----------------
__device__ float g_P[NN*HD];      // x @ W0 (layer-1 projection)
__device__ float g_h1[NN*HD];     // layer-1 output after elu
__device__ float g_TU[NN*256];    // [U0 | U1] per src node
__device__ float g_TV[NN*256];    // [V0 | V1] per dst node
__device__ float g_tab[128*128];  // structural reward lookup: 10*(ts(do,di)+bs2)
__device__ int   g_src[NE], g_dst[NE];
__device__ int   g_degout[NN], g_degin[NN];
__device__ int   g_rps[NN+1], g_rpd[NN+1];
__device__ int   g_curs[NN], g_curd[NN];
__device__ int   g_part[2][NBLK];
__device__ int2  g_adj2[NE];      // CSR order: (dst, float_bits(rstr10))
__device__ int2  g_csc[NE];       // CSC order: (csr_pos, src)
__device__ float g_als0[NN*NH], g_ald0[NN*NH], g_als1[NN*NH], g_ald1[NN*NH];
__device__ float g_Was[HD*NH], g_Wad[HD*NH];
__device__ float g_a1c[NE], g_a2c[NE];   // attention in CSR order
__device__ float2 g_rr[NE];              // (10*r0, 10*r1) in CSR order
__device__ float2 g_Vp[2][NN];           // V*10 packed (hop0,hop1), double-buffered
__device__ float g_loss;
__device__ int   g_is64;

__device__ __forceinline__ float* sel_node(int s) {
    switch (s) { case 0: return g_P; case 1: return g_TU; default: return g_TV; }
}

// ---------------- f32x2 packed math helpers (Blackwell) ----------------
__device__ __forceinline__ ull packf2(float lo, float hi) {
    ull r;
    asm("mov.b64 %0, {%1, %2};" : "=l"(r) : "f"(lo), "f"(hi));
    return r;
}
__device__ __forceinline__ void unpackf2(ull v, float& lo, float& hi) {
    asm("mov.b64 {%0, %1}, %2;" : "=f"(lo), "=f"(hi) : "l"(v));
}
__device__ __forceinline__ void fmaf2(ull& d, ull a, ull b) {
    asm("fma.rn.f32x2 %0, %1, %2, %0;" : "+l"(d) : "l"(a), "l"(b));
}

// ---------------- helpers ----------------
__device__ __forceinline__ void olse(float& m, float& s, float q) {
    if (q > m) { s = s * __expf(m - q) + 1.f; m = q; }
    else       { s += __expf(q - m); }
}
__device__ __forceinline__ void wcomb(float& m, float& s) {
    #pragma unroll
    for (int off = 16; off; off >>= 1) {
        float mo = __shfl_xor_sync(0xffffffffu, m, off);
        float so = __shfl_xor_sync(0xffffffffu, s, off);
        float M  = fmaxf(m, mo);
        float ea = (m  == M) ? 1.f : __expf(m  - M);
        float eb = (mo == M) ? 1.f : __expf(mo - M);
        s = s * ea + so * eb; m = M;
    }
}
// 16-lane-group variants (offsets 8..1 stay within a half-warp)
__device__ __forceinline__ void wcomb16(float& m, float& s) {
    #pragma unroll
    for (int off = 8; off; off >>= 1) {
        float mo = __shfl_xor_sync(0xffffffffu, m, off);
        float so = __shfl_xor_sync(0xffffffffu, s, off);
        float M  = fmaxf(m, mo);
        float ea = (m  == M) ? 1.f : __expf(m  - M);
        float eb = (mo == M) ? 1.f : __expf(mo - M);
        s = s * ea + so * eb; m = M;
    }
}
__device__ __forceinline__ float wsum(float v) {
    #pragma unroll
    for (int off = 16; off; off >>= 1) v += __shfl_xor_sync(0xffffffffu, v, off);
    return v;
}
__device__ __forceinline__ float wsum16(float v) {
    #pragma unroll
    for (int off = 8; off; off >>= 1) v += __shfl_xor_sync(0xffffffffu, v, off);
    return v;
}
__device__ __forceinline__ int wsumi(int v) {
    #pragma unroll
    for (int off = 16; off; off >>= 1) v += __shfl_xor_sync(0xffffffffu, v, off);
    return v;
}

// ---------------- kernels ----------------
__global__ void k_init() {
    int i = blockIdx.x * blockDim.x + threadIdx.x;
    if (i < NN) { g_degout[i] = 0; g_degin[i] = 0; }
    if (i == 0) { g_loss = 0.f; g_is64 = 1; }
}

__global__ void k_detect(const int* __restrict__ ei32) {
    int i = blockIdx.x * blockDim.x + threadIdx.x;
    if (i < 65536) {
        if (ei32[2 * i + 1] != 0) g_is64 = 0;
    }
}

// Structural reward lookup table: tab[do][di] = 10*(mlp2([do,di,log1p,log1p])+bs2)
__global__ void k_tab(const float* __restrict__ Ws1, const float* __restrict__ bs1,
                      const float* __restrict__ ws2, const float* __restrict__ b2s) {
    int gw = (int)((blockIdx.x * blockDim.x + threadIdx.x) >> 5);
    int lane = threadIdx.x & 31;
    int nw = (int)((gridDim.x * blockDim.x) >> 5);
    float w1[4], w2[4], w3[4], w4[4], bb[4], wk[4];
    #pragma unroll
    for (int j = 0; j < 4; j++) {
        int k = lane * 4 + j;
        w1[j] = Ws1[k]; w2[j] = Ws1[128 + k]; w3[j] = Ws1[256 + k]; w4[j] = Ws1[384 + k];
        bb[j] = bs1[k]; wk[j] = ws2[k];
    }
    float b2v = *b2s;
    for (int e = gw; e < 128 * 128; e += nw) {
        int dO = e >> 7, dI = e & 127;
        float fo = (float)dO, fi = (float)dI;
        float lo = log1pf(fo), li = log1pf(fi);
        float t = 0.f;
        #pragma unroll
        for (int j = 0; j < 4; j++) {
            float us = fo * w1[j] + lo * w3[j] + bb[j];
            float vs = fi * w2[j] + li * w4[j];
            t += fmaxf(us + vs, 0.f) * wk[j];
        }
        t = wsum(t);
        if (lane == 0) g_tab[e] = 10.f * (t + b2v);
    }
}

__global__ void k_prep(const void* __restrict__ eiv) {
    int e = blockIdx.x * blockDim.x + threadIdx.x;
    if (e >= NE) return;
    int s, d;
    if (g_is64) {
        const long long* ei = (const long long*)eiv;
        s = (int)ei[e]; d = (int)ei[NE + e];
    } else {
        const int* ei = (const int*)eiv;
        s = ei[e]; d = ei[NE + e];
    }
    s = min(max(s, 0), NN - 1);
    d = min(max(d, 0), NN - 1);
    g_src[e] = s; g_dst[e] = d;
    atomicAdd(&g_degout[s], 1);
    atomicAdd(&g_degin[d], 1);
}

__global__ void k_scan1() {
    int a = blockIdx.x >= NBLK;
    int b = blockIdx.x - a * NBLK;
    const int* deg = a ? g_degin : g_degout;
    int i = b * 256 + threadIdx.x;
    int v = (i < NN) ? deg[i] : 0;
    __shared__ int sw[8];
    int ws = wsumi(v);
    if ((threadIdx.x & 31) == 0) sw[threadIdx.x >> 5] = ws;
    __syncthreads();
    if (threadIdx.x == 0) {
        int t = 0;
        #pragma unroll
        for (int j = 0; j < 8; j++) t += sw[j];
        g_part[a][b] = t;
    }
}

__global__ void k_scan2() {
    int a = threadIdx.x >> 8;
    int t = threadIdx.x & 255;
    __shared__ int sh[2][256];
    int v = (t < NBLK) ? g_part[a][t] : 0;
    sh[a][t] = v;
    __syncthreads();
    for (int off = 1; off < 256; off <<= 1) {
        int u = (t >= off) ? sh[a][t - off] : 0;
        __syncthreads();
        sh[a][t] += u;
        __syncthreads();
    }
    if (t < NBLK) g_part[a][t] = sh[a][t] - v;
    if (t == 255) {
        if (a) g_rpd[NN] = sh[1][255]; else g_rps[NN] = sh[0][255];
    }
}

__global__ void k_scan3() {
    int a = blockIdx.x >= NBLK;
    int b = blockIdx.x - a * NBLK;
    const int* deg = a ? g_degin : g_degout;
    int* rp  = a ? g_rpd  : g_rps;
    int* cur = a ? g_curd : g_curs;
    int i = b * 256 + threadIdx.x;
    int v = (i < NN) ? deg[i] : 0;
    __shared__ int sh[256];
    sh[threadIdx.x] = v;
    __syncthreads();
    for (int off = 1; off < 256; off <<= 1) {
        int u = (threadIdx.x >= off) ? sh[threadIdx.x - off] : 0;
        __syncthreads();
        sh[threadIdx.x] += u;
        __syncthreads();
    }
    if (i < NN) {
        int excl = sh[threadIdx.x] - v + g_part[a][b];
        rp[i] = excl; cur[i] = excl;
    }
}

__global__ void k_fill() {
    int e = blockIdx.x * blockDim.x + threadIdx.x;
    if (e >= NE) return;
    int s = g_src[e], d = g_dst[e];
    int dO = g_degout[s], dI = g_degin[d];
    float r = (dO < 128 && dI < 128) ? g_tab[dO * 128 + dI]
                                     : __int_as_float(0x7fc00000);  // NaN sentinel
    int p = atomicAdd(&g_curs[s], 1);
    g_adj2[p] = make_int2(d, __float_as_int(r));
    int q = atomicAdd(&g_curd[d], 1);
    g_csc[q] = make_int2(p, s);
}

// Batched GEMM: up to 3 (dsel,coff,B,bias) configs selected by blockIdx.y,
// sharing A. 128x128 tile, 8x8 micro via fma.rn.f32x2. Double-buffered smem:
// B tiles via cp.async, A tiles prefetched one tile ahead.
__global__ void __launch_bounds__(256, 2) k_gemmB(
        const float* __restrict__ aext,
        int d0, int c0, const float* __restrict__ B0, const float* __restrict__ bias0,
        int d1, int c1, const float* __restrict__ B1, const float* __restrict__ bias1,
        int d2, int c2, const float* __restrict__ B2, const float* __restrict__ bias2,
        int M) {
    const float* A = aext ? aext : g_h1;
    int dsel, coff;
    const float *B, *bias;
    if (blockIdx.y == 0)      { dsel = d0; coff = c0; B = B0; bias = bias0; }
    else if (blockIdx.y == 1) { dsel = d1; coff = c1; B = B1; bias = bias1; }
    else                      { dsel = d2; coff = c2; B = B2; bias = bias2; }
    float* C = sel_node(dsel);
    int cs = (dsel == 0) ? 128 : 256;
    __shared__ float Ast[2][16][136];
    __shared__ float Bs[2][16][128];
    int bm = blockIdx.x * 128;
    int tid = threadIdx.x;
    int tr = tid >> 4, tc = tid & 15;
    int ar = tid >> 2, ac = (tid & 3) << 2;
    int br = tid >> 5, bc = (tid & 31) << 2;
    ull acc[8][4];
    #pragma unroll
    for (int i = 0; i < 8; i++)
        #pragma unroll
        for (int j = 0; j < 4; j++) acc[i][j] = 0ull;

    float4 pa0, pa1;

    {
        float4 v0 = make_float4(0.f, 0.f, 0.f, 0.f), v1 = v0;
        if (bm + ar < M)       v0 = *(const float4*)&A[(size_t)(bm + ar) * HD + ac];
        if (bm + ar + 64 < M)  v1 = *(const float4*)&A[(size_t)(bm + ar + 64) * HD + ac];
        Ast[0][ac][ar] = v0.x; Ast[0][ac+1][ar] = v0.y; Ast[0][ac+2][ar] = v0.z; Ast[0][ac+3][ar] = v0.w;
        Ast[0][ac][ar+64] = v1.x; Ast[0][ac+1][ar+64] = v1.y; Ast[0][ac+2][ar+64] = v1.z; Ast[0][ac+3][ar+64] = v1.w;
        __pipeline_memcpy_async(&Bs[0][br][bc],     &B[(size_t)br * HD + bc], 16);
        __pipeline_memcpy_async(&Bs[0][br + 8][bc], &B[(size_t)(br + 8) * HD + bc], 16);
        __pipeline_commit();
        __pipeline_wait_prior(0);
        pa0 = make_float4(0.f, 0.f, 0.f, 0.f); pa1 = pa0;
        if (bm + ar < M)       pa0 = *(const float4*)&A[(size_t)(bm + ar) * HD + 16 + ac];
        if (bm + ar + 64 < M)  pa1 = *(const float4*)&A[(size_t)(bm + ar + 64) * HD + 16 + ac];
        __pipeline_memcpy_async(&Bs[1][br][bc],     &B[(size_t)(16 + br) * HD + bc], 16);
        __pipeline_memcpy_async(&Bs[1][br + 8][bc], &B[(size_t)(16 + br + 8) * HD + bc], 16);
        __pipeline_commit();
        __syncthreads();
    }

    #pragma unroll 1
    for (int t = 0; t < 8; t++) {
        int cur = t & 1;
        #pragma unroll
        for (int k = 0; k < 16; k++) {
            float4 a0 = *(float4*)&Ast[cur][k][tr * 8];
            float4 a1 = *(float4*)&Ast[cur][k][tr * 8 + 4];
            float4 b0 = *(float4*)&Bs[cur][k][tc * 8];
            float4 b1 = *(float4*)&Bs[cur][k][tc * 8 + 4];
            ull b2[4] = { packf2(b0.x, b0.y), packf2(b0.z, b0.w),
                          packf2(b1.x, b1.y), packf2(b1.z, b1.w) };
            float av[8] = {a0.x, a0.y, a0.z, a0.w, a1.x, a1.y, a1.z, a1.w};
            #pragma unroll
            for (int i = 0; i < 8; i++) {
                ull af = packf2(av[i], av[i]);
                #pragma unroll
                for (int j = 0; j < 4; j++) fmaf2(acc[i][j], af, b2[j]);
            }
        }
        if (t < 7) {
            int nxt = cur ^ 1;
            __syncthreads();
            Ast[nxt][ac][ar] = pa0.x; Ast[nxt][ac+1][ar] = pa0.y;
            Ast[nxt][ac+2][ar] = pa0.z; Ast[nxt][ac+3][ar] = pa0.w;
            Ast[nxt][ac][ar+64] = pa1.x; Ast[nxt][ac+1][ar+64] = pa1.y;
            Ast[nxt][ac+2][ar+64] = pa1.z; Ast[nxt][ac+3][ar+64] = pa1.w;
            __pipeline_wait_prior(0);
            if (t < 6) {
                int k0 = (t + 2) * 16;
                pa0 = make_float4(0.f, 0.f, 0.f, 0.f); pa1 = pa0;
                if (bm + ar < M)      pa0 = *(const float4*)&A[(size_t)(bm + ar) * HD + k0 + ac];
                if (bm + ar + 64 < M) pa1 = *(const float4*)&A[(size_t)(bm + ar + 64) * HD + k0 + ac];
                __pipeline_memcpy_async(&Bs[cur][br][bc],     &B[(size_t)(k0 + br) * HD + bc], 16);
                __pipeline_memcpy_async(&Bs[cur][br + 8][bc], &B[(size_t)(k0 + br + 8) * HD + bc], 16);
                __pipeline_commit();
            }
            __syncthreads();
        }
    }
    #pragma unroll
    for (int i = 0; i < 8; i++) {
        int row = bm + tr * 8 + i;
        if (row < M) {
            #pragma unroll
            for (int j = 0; j < 4; j++) {
                float lo, hi;
                unpackf2(acc[i][j], lo, hi);
                int col = tc * 8 + j * 2;
                if (bias) { lo += bias[col]; hi += bias[col + 1]; }
                C[(size_t)row * cs + coff + col]     = lo;
                C[(size_t)row * cs + coff + col + 1] = hi;
            }
        }
    }
}

// al_s0/al_d0 from P (warp per node)
__global__ void k_alP(const float* __restrict__ as0, const float* __restrict__ ad0) {
    int g = blockIdx.x * blockDim.x + threadIdx.x;
    int w = g >> 5, lane = g & 31;
    if (w >= NN) return;
    int h = lane >> 2;
    int off = (lane & 3) * 4;
    float4 v = *(const float4*)&g_P[(size_t)w * HD + lane * 4];
    const float* a = &as0[h * 16 + off];
    const float* b = &ad0[h * 16 + off];
    float ps = v.x * a[0] + v.y * a[1] + v.z * a[2] + v.w * a[3];
    float pd = v.x * b[0] + v.y * b[1] + v.z * b[2] + v.w * b[3];
    ps += __shfl_xor_sync(0xffffffffu, ps, 1);
    ps += __shfl_xor_sync(0xffffffffu, ps, 2);
    pd += __shfl_xor_sync(0xffffffffu, pd, 1);
    pd += __shfl_xor_sync(0xffffffffu, pd, 2);
    if ((lane & 3) == 0) { g_als0[w * NH + h] = ps; g_ald0[w * NH + h] = pd; }
}

// GAT layer 1: softmax over incoming edges + aggregation + elu. Warp per dst node.
__global__ void __launch_bounds__(256) k_gat1() {
    __shared__ float s_at[8][256];
    __shared__ int   s_sc[8][32];
    int g = blockIdx.x * blockDim.x + threadIdx.x;
    int w = g >> 5, lane = g & 31, wl = threadIdx.x >> 5;
    if (w >= NN) return;
    int beg = g_rpd[w], end = g_rpd[w + 1];
    float ald[8];
    #pragma unroll
    for (int h = 0; h < 8; h++) ald[h] = g_ald0[w * NH + h];
    float m[8], s[8], ec[8];
    #pragma unroll
    for (int h = 0; h < 8; h++) { m[h] = -INFINITY; s[h] = 0.f; ec[h] = 0.f; }
    for (int p = beg + lane; p < end; p += 32) {
        int sn = g_csc[p].y;
        const float4* ap = (const float4*)&g_als0[sn * NH];
        float4 a0 = ap[0], a1 = ap[1];
        float ev[8] = {a0.x, a0.y, a0.z, a0.w, a1.x, a1.y, a1.z, a1.w};
        #pragma unroll
        for (int h = 0; h < 8; h++) {
            float e = ev[h] + ald[h];
            e = (e > 0.f) ? e : 0.2f * e;
            if (p - beg < 32) ec[h] = e;
            olse(m[h], s[h], e);
        }
    }
    #pragma unroll
    for (int h = 0; h < 8; h++) wcomb(m[h], s[h]);
    float lse[8];
    #pragma unroll
    for (int h = 0; h < 8; h++) lse[h] = m[h] + __logf(s[h]);

    ull accp0 = 0ull, accp1 = 0ull;
    int h0 = lane >> 2;
    for (int t0 = beg; t0 < end; t0 += 32) {
        int p = t0 + lane;
        int cnt = min(32, end - t0);
        if (p < end) {
            int2 cs = g_csc[p];
            int sn = cs.y;
            float ev[8];
            if (t0 == beg) {
                #pragma unroll
                for (int h = 0; h < 8; h++) ev[h] = ec[h];
            } else {
                const float4* ap = (const float4*)&g_als0[sn * NH];
                float4 a0 = ap[0], a1 = ap[1];
                float tv[8] = {a0.x, a0.y, a0.z, a0.w, a1.x, a1.y, a1.z, a1.w};
                #pragma unroll
                for (int h = 0; h < 8; h++) {
                    float e = tv[h] + ald[h];
                    ev[h] = (e > 0.f) ? e : 0.2f * e;
                }
            }
            float asum = 0.f;
            #pragma unroll
            for (int h = 0; h < 8; h++) {
                float a = __expf(ev[h] - lse[h]);
                s_at[wl][lane * 8 + h] = a;
                asum += a;
            }
            g_a1c[cs.x] = asum * 0.125f;
            s_sc[wl][lane] = sn;
        }
        __syncwarp();
        for (int j = 0; j < cnt; j++) {
            int sj = s_sc[wl][j];
            float a = s_at[wl][j * 8 + h0];
            float4 pv = *(const float4*)&g_P[(size_t)sj * HD + lane * 4];
            ull af = packf2(a, a);
            fmaf2(accp0, af, packf2(pv.x, pv.y));
            fmaf2(accp1, af, packf2(pv.z, pv.w));
        }
        __syncwarp();
    }
    float4 hv;
    unpackf2(accp0, hv.x, hv.y);
    unpackf2(accp1, hv.z, hv.w);
    hv.x = (hv.x > 0.f) ? hv.x : expm1f(hv.x);
    hv.y = (hv.y > 0.f) ? hv.y : expm1f(hv.y);
    hv.z = (hv.z > 0.f) ? hv.z : expm1f(hv.z);
    hv.w = (hv.w > 0.f) ? hv.w : expm1f(hv.w);
    *(float4*)&g_h1[(size_t)w * HD + lane * 4] = hv;
}

// Fold W1 with per-head attention vectors
__global__ void k_Wa(const float* __restrict__ W1, const float* __restrict__ as1,
                     const float* __restrict__ ad1) {
    int k = threadIdx.x;
    #pragma unroll
    for (int h = 0; h < 8; h++) {
        float ss = 0.f, sd = 0.f;
        #pragma unroll
        for (int d = 0; d < 16; d++) {
            float wv = W1[k * HD + h * 16 + d];
            ss += wv * as1[h * 16 + d];
            sd += wv * ad1[h * 16 + d];
        }
        g_Was[k * 8 + h] = ss;
        g_Wad[k * 8 + h] = sd;
    }
}

// al_s1/al_d1 = h1 @ Wa (warp per node)
__global__ void k_al2() {
    int g = blockIdx.x * blockDim.x + threadIdx.x;
    int w = g >> 5, lane = g & 31;
    if (w >= NN) return;
    float4 v = *(const float4*)&g_h1[(size_t)w * HD + lane * 4];
    float xv[4] = {v.x, v.y, v.z, v.w};
    float ps[8], pd[8];
    #pragma unroll
    for (int h = 0; h < 8; h++) { ps[h] = 0.f; pd[h] = 0.f; }
    #pragma unroll
    for (int j = 0; j < 4; j++) {
        int k = lane * 4 + j;
        const float* was = &g_Was[k * 8];
        const float* wad = &g_Wad[k * 8];
        #pragma unroll
        for (int h = 0; h < 8; h++) {
            ps[h] = fmaf(xv[j], was[h], ps[h]);
            pd[h] = fmaf(xv[j], wad[h], pd[h]);
        }
    }
    #pragma unroll
    for (int off = 16; off; off >>= 1)
        #pragma unroll
        for (int h = 0; h < 8; h++) {
            ps[h] += __shfl_xor_sync(0xffffffffu, ps[h], off);
            pd[h] += __shfl_xor_sync(0xffffffffu, pd[h], off);
        }
    if (lane == 0) {
        #pragma unroll
        for (int h = 0; h < 8; h++) {
            g_als1[w * NH + h] = ps[h];
            g_ald1[w * NH + h] = pd[h];
        }
    }
}

// Layer-2 attention only (a2). HALF-WARP (16 lanes) per dst node.
__global__ void k_attn2() {
    int g = blockIdx.x * blockDim.x + threadIdx.x;
    int w = g >> 4, lane = g & 15;
    if (w >= NN) return;
    int beg = g_rpd[w], end = g_rpd[w + 1];
    if (beg == end) return;
    float ald[8];
    #pragma unroll
    for (int h = 0; h < 8; h++) ald[h] = g_ald1[w * NH + h];
    float m[8], s[8], ec[8];
    #pragma unroll
    for (int h = 0; h < 8; h++) { m[h] = -INFINITY; s[h] = 0.f; ec[h] = 0.f; }
    for (int p = beg + lane; p < end; p += 16) {
        int sn = g_csc[p].y;
        const float4* ap = (const float4*)&g_als1[sn * NH];
        float4 a0 = ap[0], a1 = ap[1];
        float ev[8] = {a0.x, a0.y, a0.z, a0.w, a1.x, a1.y, a1.z, a1.w};
        #pragma unroll
        for (int h = 0; h < 8; h++) {
            float e = ev[h] + ald[h];
            e = (e > 0.f) ? e : 0.2f * e;
            if (p - beg < 16) ec[h] = e;
            olse(m[h], s[h], e);
        }
    }
    #pragma unroll
    for (int h = 0; h < 8; h++) wcomb16(m[h], s[h]);
    float lse[8];
    #pragma unroll
    for (int h = 0; h < 8; h++) lse[h] = m[h] + __logf(s[h]);
    for (int p = beg + lane; p < end; p += 16) {
        int2 cs = g_csc[p];
        float asum = 0.f;
        if (p - beg < 16) {
            #pragma unroll
            for (int h = 0; h < 8; h++) asum += __expf(ec[h] - lse[h]);
        } else {
            int sn = cs.y;
            const float4* ap = (const float4*)&g_als1[sn * NH];
            float4 a0 = ap[0], a1 = ap[1];
            float ev[8] = {a0.x, a0.y, a0.z, a0.w, a1.x, a1.y, a1.z, a1.w};
            #pragma unroll
            for (int h = 0; h < 8; h++) {
                float e = ev[h] + ald[h];
                e = (e > 0.f) ? e : 0.2f * e;
                asum += __expf(e - lse[h]);
            }
        }
        g_a2c[cs.x] = asum * 0.125f;
    }
}

// Fused semantic reward kernel + SVI iteration 0 (V0=0 => Q=r => V1=lse(r)).
__global__ void __launch_bounds__(256) k_rewards(const float* __restrict__ w2m,
                                                 const float* __restrict__ b2m,
                                                 const float* __restrict__ lam,
                                                 const float* __restrict__ Ws1,
                                                 const float* __restrict__ bs1,
                                                 const float* __restrict__ ws2,
                                                 const float* __restrict__ b2s) {
    int g = blockIdx.x * blockDim.x + threadIdx.x;
    int w = g >> 5, lane = g & 31;
    if (w >= NN) return;
    int beg = g_rps[w], end = g_rps[w + 1];
    if (beg == end) {
        if (lane == 0) g_Vp[1][w] = make_float2(0.f, 0.f);
        return;
    }
    size_t ro = (size_t)w * 256 + lane * 4;
    float4 u0 = *(const float4*)&g_TU[ro];
    float4 u1 = *(const float4*)&g_TU[ro + 128];
    float4 wm = *(const float4*)&w2m[lane * 4];
    float bm2v = *b2m, lam10 = 10.f * (*lam);
    float m0 = -INFINITY, s0 = 0.f, m1 = -INFINITY, s1 = 0.f;
    for (int p = beg; p < end; p++) {
        int2 ad = g_adj2[p];
        int d = ad.x;
        float rstr10 = __int_as_float(ad.y);
        size_t co = (size_t)d * 256 + lane * 4;
        float4 v0 = *(const float4*)&g_TV[co];
        float4 v1 = *(const float4*)&g_TV[co + 128];
        float t0 = fmaxf(u0.x + v0.x, 0.f) * wm.x + fmaxf(u0.y + v0.y, 0.f) * wm.y +
                   fmaxf(u0.z + v0.z, 0.f) * wm.z + fmaxf(u0.w + v0.w, 0.f) * wm.w;
        float t1 = fmaxf(u1.x + v1.x, 0.f) * wm.x + fmaxf(u1.y + v1.y, 0.f) * wm.y +
                   fmaxf(u1.z + v1.z, 0.f) * wm.z + fmaxf(u1.w + v1.w, 0.f) * wm.w;
        #pragma unroll
        for (int off = 16; off; off >>= 1) {
            t0 += __shfl_xor_sync(0xffffffffu, t0, off);
            t1 += __shfl_xor_sync(0xffffffffu, t1, off);
        }
        if (!(rstr10 == rstr10)) {
            float fo = (float)g_degout[w], fi = (float)g_degin[d];
            float lo = log1pf(fo), li = log1pf(fi);
            float ts = 0.f;
            #pragma unroll
            for (int j = 0; j < 4; j++) {
                int k = lane * 4 + j;
                float us = fo * Ws1[k] + lo * Ws1[256 + k] + bs1[k];
                float vs = fi * Ws1[128 + k] + li * Ws1[384 + k];
                ts += fmaxf(us + vs, 0.f) * ws2[k];
            }
            ts = wsum(ts);
            rstr10 = 10.f * (ts + *b2s);
        }
        float r0 = rstr10 + lam10 * (t0 + bm2v);
        float r1 = rstr10 + lam10 * (t1 + bm2v);
        if (lane == 0) g_rr[p] = make_float2(r0, r1);
        olse(m0, s0, r0);
        olse(m1, s1, r1);
    }
    if (lane == 0)
        g_Vp[1][w] = make_float2(m0 + __logf(s0), m1 + __logf(s1));
}

// One SVI iteration for both hops. HALF-WARP (16 lanes) per src node.
__global__ void k_svi(int rb) {
    int g = blockIdx.x * blockDim.x + threadIdx.x;
    int w = g >> 4, lane = g & 15;
    if (w >= NN) return;
    int beg = g_rps[w], end = g_rps[w + 1];
    int wb = rb ^ 1;
    if (beg == end) {
        if (lane == 0) g_Vp[wb][w] = make_float2(0.f, 0.f);
        return;
    }
    float m0 = -INFINITY, s0 = 0.f, m1 = -INFINITY, s1 = 0.f;
    for (int p = beg + lane; p < end; p += 16) {
        float2 r = g_rr[p];
        float2 V = g_Vp[rb][g_adj2[p].x];
        olse(m0, s0, r.x + V.x);
        olse(m1, s1, r.y + V.y);
    }
    wcomb16(m0, s0);
    wcomb16(m1, s1);
    if (lane == 0)
        g_Vp[wb][w] = make_float2(m0 + __logf(s0), m1 + __logf(s1));
}

// Final: logz & log_pi_obs lse, then per-node NLL + KL score.
// HALF-WARP (16 lanes) per src node.
__global__ void k_finalize(float* __restrict__ outs, int write_score) {
    int g = blockIdx.x * blockDim.x + threadIdx.x;
    int w = g >> 4, lane = g & 15;
    if (w >= NN) return;
    int beg = g_rps[w], end = g_rps[w + 1];
    if (beg == end) {
        if (lane == 0 && write_score) outs[w] = 0.f;
        return;
    }
    float mq0 = -INFINITY, sq0 = 0.f, mq1 = -INFINITY, sq1 = 0.f;
    float mo0 = -INFINITY, so0 = 0.f, mo1 = -INFINITY, so1 = 0.f;
    float cq0 = 0.f, cq1 = 0.f, cl0 = 0.f, cl1 = 0.f;
    for (int p = beg + lane; p < end; p += 16) {
        float2 r = g_rr[p];
        float2 V = g_Vp[1][g_adj2[p].x];
        float q0 = r.x + V.x;
        float q1 = r.y + V.y;
        float l0 = __logf(g_a1c[p] + 1e-12f);
        float l1 = __logf(g_a2c[p] + 1e-12f);
        if (p - beg < 16) { cq0 = q0; cq1 = q1; cl0 = l0; cl1 = l1; }
        olse(mq0, sq0, q0); olse(mq1, sq1, q1);
        olse(mo0, so0, l0); olse(mo1, so1, l1);
    }
    wcomb16(mq0, sq0); wcomb16(mq1, sq1);
    wcomb16(mo0, so0); wcomb16(mo1, so1);
    float logz0 = mq0 + __logf(sq0), logz1 = mq1 + __logf(sq1);
    float lseo0 = mo0 + __logf(so0), lseo1 = mo1 + __logf(so1);
    float nll = 0.f, sc = 0.f;
    for (int p = beg + lane; p < end; p += 16) {
        float q0, q1, l0, l1;
        if (p - beg < 16) { q0 = cq0; q1 = cq1; l0 = cl0; l1 = cl1; }
        else {
            float2 r = g_rr[p];
            float2 V = g_Vp[1][g_adj2[p].x];
            q0 = r.x + V.x;
            q1 = r.y + V.y;
            l0 = __logf(g_a1c[p] + 1e-12f);
            l1 = __logf(g_a2c[p] + 1e-12f);
        }
        float lpo0 = l0 - lseo0, lps0 = q0 - logz0;
        float lpo1 = l1 - lseo1, lps1 = q1 - logz1;
        float p0 = __expf(lpo0), p1 = __expf(lpo1);
        nll += p0 * lps0 + p1 * lps1;
        sc  += p0 * (lpo0 - lps0) + p1 * (lpo1 - lps1);
    }
    nll = wsum16(nll);
    sc  = wsum16(sc);
    if (lane == 0) {
        if (write_score) outs[w] = sc;
        atomicAdd(&g_loss, -nll);
    }
}

__global__ void k_out(float* __restrict__ out) {
    if (threadIdx.x == 0 && blockIdx.x == 0) out[0] = g_loss / (float)NN;
}

// ---------------- host launcher ----------------
extern "C" void kernel_launch(void* const* d_in, const int* in_sizes, int n_in,
                              void* d_out, int out_size) {
    const float*     x   = (const float*)d_in[0];
    const void*      ei  = d_in[1];
    const float*     W0  = (const float*)d_in[2];
    const float*     as0 = (const float*)d_in[3];
    const float*     ad0 = (const float*)d_in[4];
    const float*     W1  = (const float*)d_in[5];
    const float*     as1 = (const float*)d_in[6];
    const float*     ad1 = (const float*)d_in[7];
    const float*     Ws1 = (const float*)d_in[8];
    const float*     bs1 = (const float*)d_in[9];
    const float*     ws2 = (const float*)d_in[10];
    const float*     bs2 = (const float*)d_in[11];
    const float*     Wm1 = (const float*)d_in[12];
    const float*     bm1 = (const float*)d_in[13];
    const float*     wm2 = (const float*)d_in[14];
    const float*     bm2 = (const float*)d_in[15];
    const float*     lam = (const float*)d_in[16];
    float* out = (float*)d_out;

    const int TB = 256;
    int bN    = (NN + TB - 1) / TB;
    int bE    = (NE + TB - 1) / TB;
    int bNW   = (NN * 32 + TB - 1) / TB;   // warp-per-node
    int bNW16 = (NN * 16 + TB - 1) / TB;   // half-warp-per-node
    int bG    = (NN + 127) / 128;

    static cudaStream_t s1 = nullptr, s2 = nullptr;
    static cudaEvent_t eF0 = nullptr, eJ1 = nullptr, eF1 = nullptr, eJ2 = nullptr;
    if (!s1) {
        cudaStreamCreateWithFlags(&s1, cudaStreamNonBlocking);
        cudaStreamCreateWithFlags(&s2, cudaStreamNonBlocking);
        cudaEventCreateWithFlags(&eF0, cudaEventDisableTiming);
        cudaEventCreateWithFlags(&eJ1, cudaEventDisableTiming);
        cudaEventCreateWithFlags(&eF1, cudaEventDisableTiming);
        cudaEventCreateWithFlags(&eJ2, cudaEventDisableTiming);
    }
    cudaStream_t s0 = 0;

    // ---- fork s1: graph build, concurrent with x-GEMM on s0 ----
    cudaEventRecord(eF0, s0);
    cudaStreamWaitEvent(s1, eF0, 0);
    k_init<<<bN, TB, 0, s1>>>();
    k_detect<<<256, 256, 0, s1>>>((const int*)ei);
    k_tab<<<64, 256, 0, s1>>>(Ws1, bs1, ws2, bs2);
    k_prep<<<bE, TB, 0, s1>>>(ei);
    k_scan1<<<2 * NBLK, 256, 0, s1>>>();
    k_scan2<<<1, 512, 0, s1>>>();
    k_scan3<<<2 * NBLK, 256, 0, s1>>>();
    k_fill<<<bE, TB, 0, s1>>>();
    k_Wa<<<1, 128, 0, s1>>>(W1, as1, ad1);

    // s0: batched x-GEMM (P, U0, V0) + alP
    k_gemmB<<<dim3(bG, 3), TB, 0, s0>>>(x,
        0, 0, W0,             nullptr,
        1, 0, Wm1,            bm1,
        2, 0, Wm1 + 128 * HD, nullptr,
        NN);
    k_alP<<<bNW, TB, 0, s0>>>(as0, ad0);

    cudaEventRecord(eJ1, s1);
    cudaStreamWaitEvent(s0, eJ1, 0);

    k_gat1<<<bNW, TB, 0, s0>>>();

    // ---- fork s2: al2+attn2 (only needed by finalize), concurrent with
    //      h1-GEMM + rewards + svi chain on s0 ----
    cudaEventRecord(eF1, s0);
    cudaStreamWaitEvent(s2, eF1, 0);
    k_al2<<<bNW, TB, 0, s2>>>();
    k_attn2<<<bNW16, TB, 0, s2>>>();

    // s0: h1-GEMM (U1, V1) -> rewards -> svi x4
    k_gemmB<<<dim3(bG, 2), TB, 0, s0>>>(nullptr,
        1, 128, Wm1,            bm1,
        2, 128, Wm1 + 128 * HD, nullptr,
        0, 0,   Wm1,            nullptr,
        NN);
    k_rewards<<<bNW, TB, 0, s0>>>(wm2, bm2, lam, Ws1, bs1, ws2, bs2);
    for (int it = 1; it < 5; it++) k_svi<<<bNW16, TB, 0, s0>>>(it & 1);

    // join s2 before finalize (needs g_a2c)
    cudaEventRecord(eJ2, s2);
    cudaStreamWaitEvent(s0, eJ2, 0);

    if (out_size >= NN + 1) {
        k_finalize<<<bNW16, TB, 0, s0>>>(out + 1, 1);
        k_out<<<1, 32, 0, s0>>>(out);
    } else if (out_size == NN) {
        k_finalize<<<bNW16, TB, 0, s0>>>(out, 1);
    } else {
        k_finalize<<<bNW16, TB, 0, s0>>>(out, 0);
        k_out<<<1, 32, 0, s0>>>(out);
    }
}